// round 6
// baseline (speedup 1.0000x reference)
#include <cuda_runtime.h>
#include <cuda_fp16.h>
#include <cstdint>
#include <cstdio>

#define NN 50000
#define EE 800000
#define HH 128
#define GG 512
#define NBLK ((NN + 1023) / 1024)        // 49
#define GEMM_BLOCKS ((NN + 127) / 128)   // 391

// ---------------- device scratch (no allocations allowed) ----------------
__device__ __half d_xhi[NN * HH];
__device__ __half d_xlo[NN * HH];
__device__ __half d_yhi[NN * HH];
__device__ __half d_ylo[NN * HH];
__device__ __half d_agghi[NN * HH];
__device__ __half d_agglo[NN * HH];
__device__ int    d_count[NN];
__device__ int    d_rowptr[NN + 1];
__device__ int    d_cursor[NN];
__device__ int    d_csrsrc[EE];
__device__ float  d_deginv[NN];
__device__ int    d_start[GG + 1];
__device__ float  d_g[GG * HH];
__device__ int    d_partial[64];
// transposed + fp16-split weights: [3 layers][128 n][256 k]
__device__ __half d_wthi[3 * 128 * 256];
__device__ __half d_wtlo[3 * 128 * 256];

// ---------------- helpers ----------------
__device__ __forceinline__ float4 add4(float4 a, float4 b) {
    return make_float4(a.x + b.x, a.y + b.y, a.z + b.z, a.w + b.w);
}
__device__ __forceinline__ uint32_t cvta_smem(const void* p) {
    uint32_t a;
    asm("{ .reg .u64 t; cvta.to.shared.u64 t, %1; cvt.u32.u64 %0, t; }" : "=r"(a) : "l"(p));
    return a;
}
__device__ __forceinline__ void ldsm4(uint32_t* r, uint32_t addr) {
    asm volatile("ldmatrix.sync.aligned.m8n8.x4.shared.b16 {%0,%1,%2,%3}, [%4];"
                 : "=r"(r[0]), "=r"(r[1]), "=r"(r[2]), "=r"(r[3]) : "r"(addr));
}
__device__ __forceinline__ void mma16816(float* c, const uint32_t* a, const uint32_t* b) {
    asm volatile(
        "mma.sync.aligned.m16n8k16.row.col.f32.f16.f16.f32 "
        "{%0,%1,%2,%3}, {%4,%5,%6,%7}, {%8,%9}, {%0,%1,%2,%3};"
        : "+f"(c[0]), "+f"(c[1]), "+f"(c[2]), "+f"(c[3])
        : "r"(a[0]), "r"(a[1]), "r"(a[2]), "r"(a[3]), "r"(b[0]), "r"(b[1]));
}
__device__ __forceinline__ void cp16(uint32_t dst, const void* src, int src_bytes) {
    asm volatile("cp.async.cg.shared.global [%0], [%1], 16, %2;"
                 :: "r"(dst), "l"(src), "r"(src_bytes) : "memory");
}
__device__ __forceinline__ void cp_commit_wait() {
    asm volatile("cp.async.commit_group;" ::: "memory");
    asm volatile("cp.async.wait_group 0;" ::: "memory");
}
__device__ __forceinline__ uint32_t packsplit_hi(float a, float b, uint32_t* lo) {
    __half h0 = __float2half_rn(a);
    __half h1 = __float2half_rn(b);
    __half l0 = __float2half_rn(a - __half2float(h0));
    __half l1 = __float2half_rn(b - __half2float(h1));
    *lo = (uint32_t)__half_as_ushort(l0) | ((uint32_t)__half_as_ushort(l1) << 16);
    return (uint32_t)__half_as_ushort(h0) | ((uint32_t)__half_as_ushort(h1) << 16);
}

// ---------------- embedding gather + fp16 split ----------------
__global__ void embed_kernel(const int* __restrict__ z,
                             const float* __restrict__ z_emb,
                             __half* __restrict__ xhi,
                             __half* __restrict__ xlo) {
    int idx = blockIdx.x * blockDim.x + threadIdx.x;   // NN*32, 4 els each
    if (idx >= NN * 32) return;
    int n  = idx >> 5;
    int c4 = idx & 31;
    int zn = z[n];
    float4 v = reinterpret_cast<const float4*>(z_emb)[(size_t)zn * 32 + c4];
    uint2 hv, lv;
    hv.x = packsplit_hi(v.x, v.y, &lv.x);
    hv.y = packsplit_hi(v.z, v.w, &lv.y);
    reinterpret_cast<uint2*>(xhi)[idx] = hv;
    reinterpret_cast<uint2*>(xlo)[idx] = lv;
}

__global__ void zero_count_kernel(int* __restrict__ count) {
    int i = blockIdx.x * blockDim.x + threadIdx.x;
    if (i < NN) count[i] = 0;
}

__global__ void hist_kernel(const int* __restrict__ dst, int* __restrict__ count) {
    int e = blockIdx.x * blockDim.x + threadIdx.x;
    if (e < EE) atomicAdd(&count[dst[e]], 1);
}

// ---------------- parallel 3-phase scan ----------------
__global__ __launch_bounds__(1024)
void scan_blocks_kernel(const int* __restrict__ count,
                        int* __restrict__ rowptr,
                        int* __restrict__ partial) {
    __shared__ int warp_sums[32];
    int gid = blockIdx.x * 1024 + threadIdx.x;
    int lane = threadIdx.x & 31;
    int wid  = threadIdx.x >> 5;
    int v = (gid < NN) ? count[gid] : 0;
    int incl = v;
    #pragma unroll
    for (int off = 1; off < 32; off <<= 1) {
        int t = __shfl_up_sync(0xFFFFFFFFu, incl, off);
        if (lane >= off) incl += t;
    }
    if (lane == 31) warp_sums[wid] = incl;
    __syncthreads();
    if (wid == 0) {
        int ws = warp_sums[lane];
        #pragma unroll
        for (int off = 1; off < 32; off <<= 1) {
            int t = __shfl_up_sync(0xFFFFFFFFu, ws, off);
            if (lane >= off) ws += t;
        }
        warp_sums[lane] = ws;
    }
    __syncthreads();
    int excl = incl - v + (wid > 0 ? warp_sums[wid - 1] : 0);
    if (gid < NN) rowptr[gid] = excl;
    if (threadIdx.x == 1023) partial[blockIdx.x] = excl + v;
}

__global__ void scan_partials_kernel(int* __restrict__ partial) {
    int lane = threadIdx.x;
    int carry = 0;
    for (int base = 0; base < NBLK; base += 32) {
        int i = base + lane;
        int v = (i < NBLK) ? partial[i] : 0;
        int incl = v;
        #pragma unroll
        for (int off = 1; off < 32; off <<= 1) {
            int t = __shfl_up_sync(0xFFFFFFFFu, incl, off);
            if (lane >= off) incl += t;
        }
        if (i < NBLK) partial[i] = incl - v + carry;
        carry += __shfl_sync(0xFFFFFFFFu, incl, 31);
    }
}

__global__ __launch_bounds__(1024)
void scan_finalize_kernel(const int* __restrict__ count,
                          const int* __restrict__ partial,
                          int* __restrict__ rowptr,
                          int* __restrict__ cursor,
                          float* __restrict__ deginv) {
    int gid = blockIdx.x * 1024 + threadIdx.x;
    if (gid < NN) {
        int r = rowptr[gid] + partial[blockIdx.x];
        rowptr[gid] = r;
        cursor[gid] = r;
        deginv[gid] = 1.0f / (float)max(count[gid], 1);
    }
    if (gid == 0) rowptr[NN] = EE;
}

__global__ void fill_csr_kernel(const int* __restrict__ src,
                                const int* __restrict__ dst,
                                int* __restrict__ cursor,
                                int* __restrict__ csrsrc) {
    int e = blockIdx.x * blockDim.x + threadIdx.x;
    if (e >= EE) return;
    int d = dst[e];
    int pos = atomicAdd(&cursor[d], 1);
    csrsrc[pos] = src[e];
}

// ---------------- mean aggregation: fp16-hi gather, split fp16 output -------
__global__ void aggregate_kernel(const __half* __restrict__ xhi,
                                 const int* __restrict__ rowptr,
                                 const int* __restrict__ csrsrc,
                                 const float* __restrict__ deginv,
                                 __half* __restrict__ agghi,
                                 __half* __restrict__ agglo) {
    int node = blockIdx.x * blockDim.y + threadIdx.y;
    if (node >= NN) return;
    int lane = threadIdx.x;
    int beg = rowptr[node];
    int end = rowptr[node + 1];
    const uint2* xv = reinterpret_cast<const uint2*>(xhi);
    float4 a0 = make_float4(0, 0, 0, 0);
    float4 a1 = make_float4(0, 0, 0, 0);
    int j = beg;
    for (; j + 1 < end; j += 2) {
        int s0 = __ldg(&csrsrc[j]);
        int s1 = __ldg(&csrsrc[j + 1]);
        uint2 v0 = xv[(size_t)s0 * 32 + lane];
        uint2 v1 = xv[(size_t)s1 * 32 + lane];
        float2 p00 = __half22float2(*(__half2*)&v0.x);
        float2 p01 = __half22float2(*(__half2*)&v0.y);
        float2 p10 = __half22float2(*(__half2*)&v1.x);
        float2 p11 = __half22float2(*(__half2*)&v1.y);
        a0.x += p00.x; a0.y += p00.y; a0.z += p01.x; a0.w += p01.y;
        a1.x += p10.x; a1.y += p10.y; a1.z += p11.x; a1.w += p11.y;
    }
    if (j < end) {
        int s0 = __ldg(&csrsrc[j]);
        uint2 v0 = xv[(size_t)s0 * 32 + lane];
        float2 p00 = __half22float2(*(__half2*)&v0.x);
        float2 p01 = __half22float2(*(__half2*)&v0.y);
        a0.x += p00.x; a0.y += p00.y; a0.z += p01.x; a0.w += p01.y;
    }
    float di = deginv[node];
    float4 acc = add4(a0, a1);
    acc.x *= di; acc.y *= di; acc.z *= di; acc.w *= di;
    uint2 hv, lv;
    hv.x = packsplit_hi(acc.x, acc.y, &lv.x);
    hv.y = packsplit_hi(acc.z, acc.w, &lv.y);
    reinterpret_cast<uint2*>(agghi)[(size_t)node * 32 + lane] = hv;
    reinterpret_cast<uint2*>(agglo)[(size_t)node * 32 + lane] = lv;
}

// ---------------- weight transpose + fp16 split ----------------
__global__ void wcvt_kernel(const float* __restrict__ Wl,
                            const float* __restrict__ Wr,
                            __half* __restrict__ whi,
                            __half* __restrict__ wlo) {
    int i = blockIdx.x * blockDim.x + threadIdx.x;   // 32768
    if (i >= 32768) return;
    int n = i >> 8;
    int k = i & 255;
    float v = (k < 128) ? Wl[(size_t)k * HH + n] : Wr[(size_t)(k - 128) * HH + n];
    __half h = __float2half_rn(v);
    __half l = __float2half_rn(v - __half2float(h));
    whi[i] = h;
    wlo[i] = l;
}

// ---------------- HMMA SAGE GEMM (fp16 split, cp.async staging) -----------
#define AST 72   // smem row stride in halfs (144B)
#define SA_HI 0
#define SA_LO 18432
#define SW_HI 36864
#define SW_LO 55296
#define SM_BIAS 73728
#define GEMM_SMEM (73728 + 512)

__global__ __launch_bounds__(256)
void sage_mma_gemm_kernel(const __half* __restrict__ Ahi0,  // agg hi [N,128]
                          const __half* __restrict__ Alo0,
                          const __half* __restrict__ Ahi1,  // x hi
                          const __half* __restrict__ Alo1,
                          const __half* __restrict__ wthi,  // [128][256]
                          const __half* __restrict__ wtlo,
                          const float* __restrict__ bias,
                          __half* __restrict__ outhi,
                          __half* __restrict__ outlo,
                          int nrows, int do_relu) {
    extern __shared__ char sm[];
    uint32_t sbase = cvta_smem(sm);
    float* bias_sm = (float*)(sm + SM_BIAS);

    int tid  = threadIdx.x;
    int lane = tid & 31;
    int wid  = tid >> 5;
    int warp_m = wid & 3;
    int warp_n = wid >> 2;
    int block_row = blockIdx.x * 128;

    if (tid < 128) bias_sm[tid] = bias[tid];

    int a_row  = warp_m * 32 + ((lane >> 3) & 1) * 8 + (lane & 7);
    int a_colb = (lane >> 4) * 8;
    int b_n    = warp_n * 64 + (lane >> 4) * 8 + (lane & 7);
    int b_kb   = ((lane >> 3) & 1) * 8;

    float acc[2][8][4];
    #pragma unroll
    for (int mf = 0; mf < 2; mf++)
        #pragma unroll
        for (int nf = 0; nf < 8; nf++)
            #pragma unroll
            for (int i = 0; i < 4; i++) acc[mf][nf][i] = 0.0f;

    for (int c = 0; c < 4; c++) {
        if (c > 0) __syncthreads();

        const __half* Ahi = (c < 2) ? Ahi0 : Ahi1;
        const __half* Alo = (c < 2) ? Alo0 : Alo1;
        int kc = (c & 1) * 64;
        // A: 128 rows x 64 halfs per plane = 1024 uint4 per plane
        #pragma unroll
        for (int it = 0; it < 4; it++) {
            int i  = tid + it * 256;
            int r  = i >> 3;
            int k8 = (i & 7) * 8;
            int grow = block_row + r;
            int sb = (grow < nrows) ? 16 : 0;
            int srow = (grow < nrows) ? grow : 0;
            size_t goff = (size_t)srow * HH + kc + k8;
            uint32_t boff = (uint32_t)(r * AST + k8) * 2;
            cp16(sbase + SA_HI + boff, Ahi + goff, sb);
            cp16(sbase + SA_LO + boff, Alo + goff, sb);
        }
        // W: 128 n x 64 halfs per plane
        #pragma unroll
        for (int it = 0; it < 4; it++) {
            int i  = tid + it * 256;
            int n  = i >> 3;
            int k8 = (i & 7) * 8;
            size_t goff = (size_t)n * 256 + c * 64 + k8;
            uint32_t boff = (uint32_t)(n * AST + k8) * 2;
            cp16(sbase + SW_HI + boff, wthi + goff, 16);
            cp16(sbase + SW_LO + boff, wtlo + goff, 16);
        }
        cp_commit_wait();
        __syncthreads();

        #pragma unroll
        for (int ks = 0; ks < 4; ks++) {
            uint32_t ah[2][4], al[2][4];
            #pragma unroll
            for (int mf = 0; mf < 2; mf++) {
                uint32_t off = (uint32_t)((a_row + mf * 16) * AST + ks * 16 + a_colb) * 2;
                ldsm4(ah[mf], sbase + SA_HI + off);
                ldsm4(al[mf], sbase + SA_LO + off);
            }
            uint32_t bh[4][4], bl[4][4];
            #pragma unroll
            for (int ng = 0; ng < 4; ng++) {
                uint32_t off = (uint32_t)((b_n + ng * 16) * AST + ks * 16 + b_kb) * 2;
                ldsm4(bh[ng], sbase + SW_HI + off);
                ldsm4(bl[ng], sbase + SW_LO + off);
            }
            #pragma unroll
            for (int mf = 0; mf < 2; mf++) {
                #pragma unroll
                for (int nf = 0; nf < 8; nf++)
                    mma16816(acc[mf][nf], ah[mf], &bh[nf >> 1][(nf & 1) * 2]);
                #pragma unroll
                for (int nf = 0; nf < 8; nf++)
                    mma16816(acc[mf][nf], ah[mf], &bl[nf >> 1][(nf & 1) * 2]);
                #pragma unroll
                for (int nf = 0; nf < 8; nf++)
                    mma16816(acc[mf][nf], al[mf], &bh[nf >> 1][(nf & 1) * 2]);
            }
        }
    }

    // --- epilogue: bias + relu, split to fp16 hi/lo planes ---
    #pragma unroll
    for (int mf = 0; mf < 2; mf++) {
        int r0 = block_row + warp_m * 32 + mf * 16 + (lane >> 2);
        #pragma unroll
        for (int nf = 0; nf < 8; nf++) {
            int col = warp_n * 64 + nf * 8 + (lane & 3) * 2;
            float v00 = acc[mf][nf][0] + bias_sm[col];
            float v01 = acc[mf][nf][1] + bias_sm[col + 1];
            float v10 = acc[mf][nf][2] + bias_sm[col];
            float v11 = acc[mf][nf][3] + bias_sm[col + 1];
            if (do_relu) {
                v00 = fmaxf(v00, 0.0f); v01 = fmaxf(v01, 0.0f);
                v10 = fmaxf(v10, 0.0f); v11 = fmaxf(v11, 0.0f);
            }
            uint32_t lo0, lo1;
            uint32_t hi0 = packsplit_hi(v00, v01, &lo0);
            uint32_t hi1 = packsplit_hi(v10, v11, &lo1);
            if (r0 < nrows) {
                *(uint32_t*)(outhi + (size_t)r0 * HH + col) = hi0;
                *(uint32_t*)(outlo + (size_t)r0 * HH + col) = lo0;
            }
            if (r0 + 8 < nrows) {
                *(uint32_t*)(outhi + (size_t)(r0 + 8) * HH + col) = hi1;
                *(uint32_t*)(outlo + (size_t)(r0 + 8) * HH + col) = lo1;
            }
        }
    }
}

// ---------------- pooling (reads hi/lo planes) ----------------
__global__ void graph_starts_kernel(const int* __restrict__ batch, int* __restrict__ start) {
    int b = blockIdx.x * blockDim.x + threadIdx.x;
    if (b > GG) return;
    if (b == GG) { start[GG] = NN; return; }
    int lo = 0, hi = NN;
    while (lo < hi) {
        int mid = (lo + hi) >> 1;
        if (batch[mid] < b) lo = mid + 1; else hi = mid;
    }
    start[b] = lo;
}

__global__ void pool_kernel(const __half* __restrict__ yhi,
                            const __half* __restrict__ ylo,
                            const int* __restrict__ start,
                            float* __restrict__ g) {
    int b = blockIdx.x;
    int s = start[b], e = start[b + 1];
    int lane = threadIdx.x;
    int w = threadIdx.y;
    const uint2* hv = reinterpret_cast<const uint2*>(yhi);
    const uint2* lv = reinterpret_cast<const uint2*>(ylo);
    float4 acc = make_float4(0, 0, 0, 0);
    for (int n = s + w; n < e; n += 8) {
        uint2 h = hv[(size_t)n * 32 + lane];
        uint2 l = lv[(size_t)n * 32 + lane];
        float2 h0 = __half22float2(*(__half2*)&h.x);
        float2 h1 = __half22float2(*(__half2*)&h.y);
        float2 l0 = __half22float2(*(__half2*)&l.x);
        float2 l1 = __half22float2(*(__half2*)&l.y);
        acc.x += h0.x + l0.x; acc.y += h0.y + l0.y;
        acc.z += h1.x + l1.x; acc.w += h1.y + l1.y;
    }
    __shared__ float4 sh[8][32];
    sh[w][lane] = acc;
    __syncthreads();
    if (w == 0) {
        float4 t = sh[0][lane];
        #pragma unroll
        for (int i = 1; i < 8; i++) t = add4(t, sh[i][lane]);
        *reinterpret_cast<float4*>(g + (size_t)b * HH + lane * 4) = t;
    }
}

// ---------------- final MLP ----------------
__global__ void mlp_kernel(const float* __restrict__ g,
                           const float* __restrict__ W1,
                           const float* __restrict__ b1,
                           const float* __restrict__ W2,
                           const float* __restrict__ b2,
                           float* __restrict__ out) {
    int b = blockIdx.x;
    int t = threadIdx.x;
    __shared__ float gs[HH];
    gs[t] = g[(size_t)b * HH + t];
    __syncthreads();
    float acc = 0.0f;
    #pragma unroll 8
    for (int k = 0; k < HH; k++)
        acc = fmaf(gs[k], W1[(size_t)k * HH + t], acc);
    float h = fmaxf(acc + b1[t], 0.0f);
    float p = h * W2[t];
    #pragma unroll
    for (int off = 16; off > 0; off >>= 1)
        p += __shfl_xor_sync(0xFFFFFFFFu, p, off);
    __shared__ float ws[4];
    if ((t & 31) == 0) ws[t >> 5] = p;
    __syncthreads();
    if (t == 0) out[b] = ws[0] + ws[1] + ws[2] + ws[3] + b2[0];
}

// ---------------- launch ----------------
extern "C" void kernel_launch(void* const* d_in, const int* in_sizes, int n_in,
                              void* d_out, int out_size) {
    const int*   z     = (const int*)d_in[0];
    const int*   ei    = (const int*)d_in[1];
    const int*   batch = (const int*)d_in[2];
    const float* z_emb = (const float*)d_in[3];
    const float* Wl[3] = {(const float*)d_in[4], (const float*)d_in[7], (const float*)d_in[10]};
    const float* bl[3] = {(const float*)d_in[5], (const float*)d_in[8], (const float*)d_in[11]};
    const float* Wr[3] = {(const float*)d_in[6], (const float*)d_in[9], (const float*)d_in[12]};
    const float* W1 = (const float*)d_in[13];
    const float* b1 = (const float*)d_in[14];
    const float* W2 = (const float*)d_in[15];
    const float* b2 = (const float*)d_in[16];
    float* out = (float*)d_out;

    __half *xhi, *xlo, *yhi, *ylo, *agghi, *agglo, *wthi, *wtlo;
    float *deginv, *g;
    int *count, *rowptr, *cursor, *csrsrc, *start, *partial;
    cudaGetSymbolAddress((void**)&xhi,    d_xhi);
    cudaGetSymbolAddress((void**)&xlo,    d_xlo);
    cudaGetSymbolAddress((void**)&yhi,    d_yhi);
    cudaGetSymbolAddress((void**)&ylo,    d_ylo);
    cudaGetSymbolAddress((void**)&agghi,  d_agghi);
    cudaGetSymbolAddress((void**)&agglo,  d_agglo);
    cudaGetSymbolAddress((void**)&deginv, d_deginv);
    cudaGetSymbolAddress((void**)&g,      d_g);
    cudaGetSymbolAddress((void**)&count,  d_count);
    cudaGetSymbolAddress((void**)&rowptr, d_rowptr);
    cudaGetSymbolAddress((void**)&cursor, d_cursor);
    cudaGetSymbolAddress((void**)&csrsrc, d_csrsrc);
    cudaGetSymbolAddress((void**)&start,  d_start);
    cudaGetSymbolAddress((void**)&partial,d_partial);
    cudaGetSymbolAddress((void**)&wthi,   d_wthi);
    cudaGetSymbolAddress((void**)&wtlo,   d_wtlo);

    cudaFuncSetAttribute(sage_mma_gemm_kernel,
                         cudaFuncAttributeMaxDynamicSharedMemorySize, GEMM_SMEM);

    const int* src = ei;
    const int* dst = ei + EE;

    embed_kernel<<<(NN * 32 + 255) / 256, 256>>>(z, z_emb, xhi, xlo);
    zero_count_kernel<<<(NN + 255) / 256, 256>>>(count);
    hist_kernel<<<(EE + 255) / 256, 256>>>(dst, count);
    scan_blocks_kernel<<<NBLK, 1024>>>(count, rowptr, partial);
    scan_partials_kernel<<<1, 32>>>(partial);
    scan_finalize_kernel<<<NBLK, 1024>>>(count, partial, rowptr, cursor, deginv);
    fill_csr_kernel<<<(EE + 255) / 256, 256>>>(src, dst, cursor, csrsrc);
    graph_starts_kernel<<<3, 256>>>(batch, start);
    for (int l = 0; l < 3; l++)
        wcvt_kernel<<<128, 256>>>(Wl[l], Wr[l],
                                  wthi + (size_t)l * 32768, wtlo + (size_t)l * 32768);

    __half *curhi = xhi, *curlo = xlo;
    __half *nxthi = yhi, *nxtlo = ylo;
    for (int l = 0; l < 3; l++) {
        aggregate_kernel<<<(NN + 7) / 8, dim3(32, 8)>>>(curhi, rowptr, csrsrc, deginv,
                                                        agghi, agglo);
        sage_mma_gemm_kernel<<<GEMM_BLOCKS, 256, GEMM_SMEM>>>(
            agghi, agglo, curhi, curlo,
            wthi + (size_t)l * 32768, wtlo + (size_t)l * 32768,
            bl[l], nxthi, nxtlo, NN, (l < 2) ? 1 : 0);
        __half* t;
        t = curhi; curhi = nxthi; nxthi = t;
        t = curlo; curlo = nxtlo; nxtlo = t;
    }

    pool_kernel<<<GG, dim3(32, 8)>>>(curhi, curlo, start, g);
    mlp_kernel<<<GG, 128>>>(g, W1, b1, W2, b2, out);
}

// round 7
// speedup vs baseline: 1.0070x; 1.0070x over previous
#include <cuda_runtime.h>
#include <cuda_bf16.h>
#include <cuda_fp16.h>
#include <cstdint>
#include <cstdio>

#define NN 50000
#define EE 800000
#define HH 128
#define GG 512
#define NBLK ((NN + 1023) / 1024)        // 49
#define GEMM_BLOCKS ((NN + 127) / 128)   // 391

// ---------------- device scratch (no allocations allowed) ----------------
__device__ float  d_x[NN * HH];
__device__ float  d_y[NN * HH];
__device__ float  d_agg[NN * HH];
__device__ __half d_xh[NN * HH];   // fp16 shadow of current activations
__device__ __half d_yh[NN * HH];
__device__ int    d_count[NN];
__device__ int    d_rowptr[NN + 1];
__device__ int    d_cursor[NN];
__device__ int    d_csrsrc[EE];
__device__ float  d_deginv[NN];
__device__ int    d_start[GG + 1];
__device__ float  d_g[GG * HH];
__device__ int    d_partial[64];
// transposed + bf16-split weights: [3 layers][128 n][256 k]
__device__ __nv_bfloat16 d_wthi[3 * 128 * 256];
__device__ __nv_bfloat16 d_wtlo[3 * 128 * 256];

// ---------------- helpers ----------------
__device__ __forceinline__ float4 add4(float4 a, float4 b) {
    return make_float4(a.x + b.x, a.y + b.y, a.z + b.z, a.w + b.w);
}
__device__ __forceinline__ uint32_t cvta_smem(const void* p) {
    uint32_t a;
    asm("{ .reg .u64 t; cvta.to.shared.u64 t, %1; cvt.u32.u64 %0, t; }" : "=r"(a) : "l"(p));
    return a;
}
__device__ __forceinline__ void ldsm4(uint32_t* r, uint32_t addr) {
    asm volatile("ldmatrix.sync.aligned.m8n8.x4.shared.b16 {%0,%1,%2,%3}, [%4];"
                 : "=r"(r[0]), "=r"(r[1]), "=r"(r[2]), "=r"(r[3]) : "r"(addr));
}
__device__ __forceinline__ void mma16816(float* c, const uint32_t* a, const uint32_t* b) {
    asm volatile(
        "mma.sync.aligned.m16n8k16.row.col.f32.bf16.bf16.f32 "
        "{%0,%1,%2,%3}, {%4,%5,%6,%7}, {%8,%9}, {%0,%1,%2,%3};"
        : "+f"(c[0]), "+f"(c[1]), "+f"(c[2]), "+f"(c[3])
        : "r"(a[0]), "r"(a[1]), "r"(a[2]), "r"(a[3]), "r"(b[0]), "r"(b[1]));
}
__device__ __forceinline__ uint32_t packh2(float a, float b) {
    __half2 h = __floats2half2_rn(a, b);
    return *(uint32_t*)&h;
}

// ---------------- embedding gather: fp32 + fp16 shadow ----------------
__global__ void embed_kernel(const int* __restrict__ z,
                             const float* __restrict__ z_emb,
                             float* __restrict__ x,
                             __half* __restrict__ xh) {
    int idx = blockIdx.x * blockDim.x + threadIdx.x;   // over NN*32 float4s
    if (idx >= NN * 32) return;
    int n  = idx >> 5;
    int c4 = idx & 31;
    int zn = z[n];
    float4 v = reinterpret_cast<const float4*>(z_emb)[(size_t)zn * 32 + c4];
    reinterpret_cast<float4*>(x)[idx] = v;
    uint2 h;
    h.x = packh2(v.x, v.y);
    h.y = packh2(v.z, v.w);
    reinterpret_cast<uint2*>(xh)[idx] = h;
}

__global__ void zero_count_kernel(int* __restrict__ count) {
    int i = blockIdx.x * blockDim.x + threadIdx.x;
    if (i < NN) count[i] = 0;
}

__global__ void hist_kernel(const int* __restrict__ dst, int* __restrict__ count) {
    int e = blockIdx.x * blockDim.x + threadIdx.x;
    if (e < EE) atomicAdd(&count[dst[e]], 1);
}

// ---------------- parallel 3-phase scan ----------------
__global__ __launch_bounds__(1024)
void scan_blocks_kernel(const int* __restrict__ count,
                        int* __restrict__ rowptr,
                        int* __restrict__ partial) {
    __shared__ int warp_sums[32];
    int gid = blockIdx.x * 1024 + threadIdx.x;
    int lane = threadIdx.x & 31;
    int wid  = threadIdx.x >> 5;
    int v = (gid < NN) ? count[gid] : 0;
    int incl = v;
    #pragma unroll
    for (int off = 1; off < 32; off <<= 1) {
        int t = __shfl_up_sync(0xFFFFFFFFu, incl, off);
        if (lane >= off) incl += t;
    }
    if (lane == 31) warp_sums[wid] = incl;
    __syncthreads();
    if (wid == 0) {
        int ws = warp_sums[lane];
        #pragma unroll
        for (int off = 1; off < 32; off <<= 1) {
            int t = __shfl_up_sync(0xFFFFFFFFu, ws, off);
            if (lane >= off) ws += t;
        }
        warp_sums[lane] = ws;
    }
    __syncthreads();
    int excl = incl - v + (wid > 0 ? warp_sums[wid - 1] : 0);
    if (gid < NN) rowptr[gid] = excl;
    if (threadIdx.x == 1023) partial[blockIdx.x] = excl + v;
}

__global__ void scan_partials_kernel(int* __restrict__ partial) {
    int lane = threadIdx.x;
    int carry = 0;
    for (int base = 0; base < NBLK; base += 32) {
        int i = base + lane;
        int v = (i < NBLK) ? partial[i] : 0;
        int incl = v;
        #pragma unroll
        for (int off = 1; off < 32; off <<= 1) {
            int t = __shfl_up_sync(0xFFFFFFFFu, incl, off);
            if (lane >= off) incl += t;
        }
        if (i < NBLK) partial[i] = incl - v + carry;
        carry += __shfl_sync(0xFFFFFFFFu, incl, 31);
    }
}

__global__ __launch_bounds__(1024)
void scan_finalize_kernel(const int* __restrict__ count,
                          const int* __restrict__ partial,
                          int* __restrict__ rowptr,
                          int* __restrict__ cursor,
                          float* __restrict__ deginv) {
    int gid = blockIdx.x * 1024 + threadIdx.x;
    if (gid < NN) {
        int r = rowptr[gid] + partial[blockIdx.x];
        rowptr[gid] = r;
        cursor[gid] = r;
        deginv[gid] = 1.0f / (float)max(count[gid], 1);
    }
    if (gid == 0) rowptr[NN] = EE;
}

__global__ void fill_csr_kernel(const int* __restrict__ src,
                                const int* __restrict__ dst,
                                int* __restrict__ cursor,
                                int* __restrict__ csrsrc) {
    int e = blockIdx.x * blockDim.x + threadIdx.x;
    if (e >= EE) return;
    int d = dst[e];
    int pos = atomicAdd(&cursor[d], 1);
    csrsrc[pos] = src[e];
}

// ---------------- mean aggregation: fp16 gather -> fp32 agg ----------------
__global__ void aggregate_kernel(const __half* __restrict__ xh,
                                 const int* __restrict__ rowptr,
                                 const int* __restrict__ csrsrc,
                                 const float* __restrict__ deginv,
                                 float* __restrict__ out) {
    int node = blockIdx.x * blockDim.y + threadIdx.y;
    if (node >= NN) return;
    int lane = threadIdx.x;
    int beg = rowptr[node];
    int end = rowptr[node + 1];
    const uint2* xv = reinterpret_cast<const uint2*>(xh);
    float4 a0 = make_float4(0, 0, 0, 0);
    float4 a1 = make_float4(0, 0, 0, 0);
    float4 a2 = make_float4(0, 0, 0, 0);
    float4 a3 = make_float4(0, 0, 0, 0);
    int j = beg;
    for (; j + 3 < end; j += 4) {
        int s0 = __ldg(&csrsrc[j]);
        int s1 = __ldg(&csrsrc[j + 1]);
        int s2 = __ldg(&csrsrc[j + 2]);
        int s3 = __ldg(&csrsrc[j + 3]);
        uint2 v0 = xv[(size_t)s0 * 32 + lane];
        uint2 v1 = xv[(size_t)s1 * 32 + lane];
        uint2 v2 = xv[(size_t)s2 * 32 + lane];
        uint2 v3 = xv[(size_t)s3 * 32 + lane];
        float2 p;
        p = __half22float2(*(__half2*)&v0.x); a0.x += p.x; a0.y += p.y;
        p = __half22float2(*(__half2*)&v0.y); a0.z += p.x; a0.w += p.y;
        p = __half22float2(*(__half2*)&v1.x); a1.x += p.x; a1.y += p.y;
        p = __half22float2(*(__half2*)&v1.y); a1.z += p.x; a1.w += p.y;
        p = __half22float2(*(__half2*)&v2.x); a2.x += p.x; a2.y += p.y;
        p = __half22float2(*(__half2*)&v2.y); a2.z += p.x; a2.w += p.y;
        p = __half22float2(*(__half2*)&v3.x); a3.x += p.x; a3.y += p.y;
        p = __half22float2(*(__half2*)&v3.y); a3.z += p.x; a3.w += p.y;
    }
    for (; j < end; j++) {
        int s0 = __ldg(&csrsrc[j]);
        uint2 v0 = xv[(size_t)s0 * 32 + lane];
        float2 p;
        p = __half22float2(*(__half2*)&v0.x); a0.x += p.x; a0.y += p.y;
        p = __half22float2(*(__half2*)&v0.y); a0.z += p.x; a0.w += p.y;
    }
    float di = deginv[node];
    float4 acc = add4(add4(a0, a1), add4(a2, a3));
    acc.x *= di; acc.y *= di; acc.z *= di; acc.w *= di;
    *reinterpret_cast<float4*>(out + (size_t)node * HH + lane * 4) = acc;
}

// ---------------- weight transpose + bf16 split ----------------
__global__ void wcvt_kernel(const float* __restrict__ Wl,
                            const float* __restrict__ Wr,
                            __nv_bfloat16* __restrict__ whi,
                            __nv_bfloat16* __restrict__ wlo) {
    int i = blockIdx.x * blockDim.x + threadIdx.x;   // 32768
    if (i >= 32768) return;
    int n = i >> 8;
    int k = i & 255;
    float v = (k < 128) ? Wl[(size_t)k * HH + n] : Wr[(size_t)(k - 128) * HH + n];
    __nv_bfloat16 h = __float2bfloat16(v);
    __nv_bfloat16 l = __float2bfloat16(v - __bfloat162float(h));
    whi[i] = h;
    wlo[i] = l;
}

// ---------------- HMMA SAGE GEMM (R5 structure + fp16 shadow write) -------
#define AST 72   // smem row stride in bf16 elements (144B: conflict-free ldmatrix)
#define SA_HI 0
#define SA_LO 18432
#define SW_HI 36864
#define SW_LO 55296
#define SM_BIAS 73728
#define GEMM_SMEM (73728 + 512)

__global__ __launch_bounds__(256)
void sage_mma_gemm_kernel(const float* __restrict__ A0,   // agg [N,128]
                          const float* __restrict__ A1,   // x   [N,128]
                          const __nv_bfloat16* __restrict__ wthi,  // [128][256]
                          const __nv_bfloat16* __restrict__ wtlo,
                          const float* __restrict__ bias,
                          float* __restrict__ out,
                          __half* __restrict__ outh,
                          int nrows, int do_relu) {
    extern __shared__ char sm[];
    uint32_t sbase = cvta_smem(sm);
    float* bias_sm = (float*)(sm + SM_BIAS);

    int tid  = threadIdx.x;
    int lane = tid & 31;
    int wid  = tid >> 5;
    int warp_m = wid & 3;
    int warp_n = wid >> 2;
    int block_row = blockIdx.x * 128;

    if (tid < 128) bias_sm[tid] = bias[tid];

    int a_row  = warp_m * 32 + ((lane >> 3) & 1) * 8 + (lane & 7);
    int a_colb = (lane >> 4) * 8;
    int b_n    = warp_n * 64 + (lane >> 4) * 8 + (lane & 7);
    int b_kb   = ((lane >> 3) & 1) * 8;

    float acc[2][8][4];
    #pragma unroll
    for (int mf = 0; mf < 2; mf++)
        #pragma unroll
        for (int nf = 0; nf < 8; nf++)
            #pragma unroll
            for (int i = 0; i < 4; i++) acc[mf][nf][i] = 0.0f;

    for (int c = 0; c < 4; c++) {
        if (c > 0) __syncthreads();

        // --- stage A chunk: 128 rows x 64 k, fp32 -> hi/lo bf16 ---
        const float* Asrc = (c < 2) ? A0 : A1;
        int kc = (c & 1) * 64;
        #pragma unroll
        for (int it = 0; it < 8; it++) {
            int i  = tid + it * 256;        // 0..2047 float4s
            int r  = i >> 4;                // 0..127
            int k4 = (i & 15) * 4;          // 0..60
            float4 v = make_float4(0, 0, 0, 0);
            int grow = block_row + r;
            if (grow < nrows)
                v = *reinterpret_cast<const float4*>(Asrc + (size_t)grow * HH + kc + k4);
            __nv_bfloat16 h0 = __float2bfloat16(v.x);
            __nv_bfloat16 h1 = __float2bfloat16(v.y);
            __nv_bfloat16 h2 = __float2bfloat16(v.z);
            __nv_bfloat16 h3 = __float2bfloat16(v.w);
            __nv_bfloat16 l0 = __float2bfloat16(v.x - __bfloat162float(h0));
            __nv_bfloat16 l1 = __float2bfloat16(v.y - __bfloat162float(h1));
            __nv_bfloat16 l2 = __float2bfloat16(v.z - __bfloat162float(h2));
            __nv_bfloat16 l3 = __float2bfloat16(v.w - __bfloat162float(h3));
            uint32_t hp0 = (uint32_t)__bfloat16_as_ushort(h0) | ((uint32_t)__bfloat16_as_ushort(h1) << 16);
            uint32_t hp1 = (uint32_t)__bfloat16_as_ushort(h2) | ((uint32_t)__bfloat16_as_ushort(h3) << 16);
            uint32_t lp0 = (uint32_t)__bfloat16_as_ushort(l0) | ((uint32_t)__bfloat16_as_ushort(l1) << 16);
            uint32_t lp1 = (uint32_t)__bfloat16_as_ushort(l2) | ((uint32_t)__bfloat16_as_ushort(l3) << 16);
            uint32_t boff = (uint32_t)(r * AST + k4) * 2;
            *(uint2*)(sm + SA_HI + boff) = make_uint2(hp0, hp1);
            *(uint2*)(sm + SA_LO + boff) = make_uint2(lp0, lp1);
        }
        // --- stage W chunk: 128 n x 64 k, pre-split bf16 (uint4 = 8 bf16) ---
        #pragma unroll
        for (int it = 0; it < 4; it++) {
            int i  = tid + it * 256;        // 0..1023
            int n  = i >> 3;                // 0..127
            int k8 = (i & 7) * 8;           // 0..56
            size_t goff = (size_t)n * 256 + c * 64 + k8;
            uint32_t boff = (uint32_t)(n * AST + k8) * 2;
            *(uint4*)(sm + SW_HI + boff) = *(const uint4*)(wthi + goff);
            *(uint4*)(sm + SW_LO + boff) = *(const uint4*)(wtlo + goff);
        }
        __syncthreads();

        // --- compute: 4 k16-steps ---
        #pragma unroll
        for (int ks = 0; ks < 4; ks++) {
            uint32_t ah[2][4], al[2][4];
            #pragma unroll
            for (int mf = 0; mf < 2; mf++) {
                uint32_t off = (uint32_t)((a_row + mf * 16) * AST + ks * 16 + a_colb) * 2;
                ldsm4(ah[mf], sbase + SA_HI + off);
                ldsm4(al[mf], sbase + SA_LO + off);
            }
            uint32_t bh[4][4], bl[4][4];
            #pragma unroll
            for (int ng = 0; ng < 4; ng++) {
                uint32_t off = (uint32_t)((b_n + ng * 16) * AST + ks * 16 + b_kb) * 2;
                ldsm4(bh[ng], sbase + SW_HI + off);
                ldsm4(bl[ng], sbase + SW_LO + off);
            }
            #pragma unroll
            for (int mf = 0; mf < 2; mf++) {
                #pragma unroll
                for (int nf = 0; nf < 8; nf++)
                    mma16816(acc[mf][nf], ah[mf], &bh[nf >> 1][(nf & 1) * 2]);
                #pragma unroll
                for (int nf = 0; nf < 8; nf++)
                    mma16816(acc[mf][nf], ah[mf], &bl[nf >> 1][(nf & 1) * 2]);
                #pragma unroll
                for (int nf = 0; nf < 8; nf++)
                    mma16816(acc[mf][nf], al[mf], &bh[nf >> 1][(nf & 1) * 2]);
            }
        }
    }

    // --- epilogue: bias + relu, fp32 store + fp16 shadow store ---
    #pragma unroll
    for (int mf = 0; mf < 2; mf++) {
        int r0 = block_row + warp_m * 32 + mf * 16 + (lane >> 2);
        #pragma unroll
        for (int nf = 0; nf < 8; nf++) {
            int col = warp_n * 64 + nf * 8 + (lane & 3) * 2;
            float2 v0 = make_float2(acc[mf][nf][0] + bias_sm[col],
                                    acc[mf][nf][1] + bias_sm[col + 1]);
            float2 v1 = make_float2(acc[mf][nf][2] + bias_sm[col],
                                    acc[mf][nf][3] + bias_sm[col + 1]);
            if (do_relu) {
                v0.x = fmaxf(v0.x, 0.0f); v0.y = fmaxf(v0.y, 0.0f);
                v1.x = fmaxf(v1.x, 0.0f); v1.y = fmaxf(v1.y, 0.0f);
            }
            if (r0 < nrows) {
                *reinterpret_cast<float2*>(out + (size_t)r0 * HH + col) = v0;
                *(uint32_t*)(outh + (size_t)r0 * HH + col) = packh2(v0.x, v0.y);
            }
            if (r0 + 8 < nrows) {
                *reinterpret_cast<float2*>(out + (size_t)(r0 + 8) * HH + col) = v1;
                *(uint32_t*)(outh + (size_t)(r0 + 8) * HH + col) = packh2(v1.x, v1.y);
            }
        }
    }
}

// ---------------- pooling ----------------
__global__ void graph_starts_kernel(const int* __restrict__ batch, int* __restrict__ start) {
    int b = blockIdx.x * blockDim.x + threadIdx.x;
    if (b > GG) return;
    if (b == GG) { start[GG] = NN; return; }
    int lo = 0, hi = NN;
    while (lo < hi) {
        int mid = (lo + hi) >> 1;
        if (batch[mid] < b) lo = mid + 1; else hi = mid;
    }
    start[b] = lo;
}

__global__ void pool_kernel(const float* __restrict__ x,
                            const int* __restrict__ start,
                            float* __restrict__ g) {
    int b = blockIdx.x;
    int s = start[b], e = start[b + 1];
    int lane = threadIdx.x;
    int w = threadIdx.y;
    float4 acc = make_float4(0, 0, 0, 0);
    for (int n = s + w; n < e; n += 8) {
        float4 v = *reinterpret_cast<const float4*>(x + (size_t)n * HH + lane * 4);
        acc = add4(acc, v);
    }
    __shared__ float4 sh[8][32];
    sh[w][lane] = acc;
    __syncthreads();
    if (w == 0) {
        float4 t = sh[0][lane];
        #pragma unroll
        for (int i = 1; i < 8; i++) t = add4(t, sh[i][lane]);
        *reinterpret_cast<float4*>(g + (size_t)b * HH + lane * 4) = t;
    }
}

// ---------------- final MLP ----------------
__global__ void mlp_kernel(const float* __restrict__ g,
                           const float* __restrict__ W1,
                           const float* __restrict__ b1,
                           const float* __restrict__ W2,
                           const float* __restrict__ b2,
                           float* __restrict__ out) {
    int b = blockIdx.x;
    int t = threadIdx.x;
    __shared__ float gs[HH];
    gs[t] = g[(size_t)b * HH + t];
    __syncthreads();
    float acc = 0.0f;
    #pragma unroll 8
    for (int k = 0; k < HH; k++)
        acc = fmaf(gs[k], W1[(size_t)k * HH + t], acc);
    float h = fmaxf(acc + b1[t], 0.0f);
    float p = h * W2[t];
    #pragma unroll
    for (int off = 16; off > 0; off >>= 1)
        p += __shfl_xor_sync(0xFFFFFFFFu, p, off);
    __shared__ float ws[4];
    if ((t & 31) == 0) ws[t >> 5] = p;
    __syncthreads();
    if (t == 0) out[b] = ws[0] + ws[1] + ws[2] + ws[3] + b2[0];
}

// ---------------- launch ----------------
extern "C" void kernel_launch(void* const* d_in, const int* in_sizes, int n_in,
                              void* d_out, int out_size) {
    const int*   z     = (const int*)d_in[0];
    const int*   ei    = (const int*)d_in[1];
    const int*   batch = (const int*)d_in[2];
    const float* z_emb = (const float*)d_in[3];
    const float* Wl[3] = {(const float*)d_in[4], (const float*)d_in[7], (const float*)d_in[10]};
    const float* bl[3] = {(const float*)d_in[5], (const float*)d_in[8], (const float*)d_in[11]};
    const float* Wr[3] = {(const float*)d_in[6], (const float*)d_in[9], (const float*)d_in[12]};
    const float* W1 = (const float*)d_in[13];
    const float* b1 = (const float*)d_in[14];
    const float* W2 = (const float*)d_in[15];
    const float* b2 = (const float*)d_in[16];
    float* out = (float*)d_out;

    float *x, *y, *agg, *deginv, *g;
    __half *xh, *yh;
    int *count, *rowptr, *cursor, *csrsrc, *start, *partial;
    __nv_bfloat16 *wthi, *wtlo;
    cudaGetSymbolAddress((void**)&x,      d_x);
    cudaGetSymbolAddress((void**)&y,      d_y);
    cudaGetSymbolAddress((void**)&agg,    d_agg);
    cudaGetSymbolAddress((void**)&xh,     d_xh);
    cudaGetSymbolAddress((void**)&yh,     d_yh);
    cudaGetSymbolAddress((void**)&deginv, d_deginv);
    cudaGetSymbolAddress((void**)&g,      d_g);
    cudaGetSymbolAddress((void**)&count,  d_count);
    cudaGetSymbolAddress((void**)&rowptr, d_rowptr);
    cudaGetSymbolAddress((void**)&cursor, d_cursor);
    cudaGetSymbolAddress((void**)&csrsrc, d_csrsrc);
    cudaGetSymbolAddress((void**)&start,  d_start);
    cudaGetSymbolAddress((void**)&partial,d_partial);
    cudaGetSymbolAddress((void**)&wthi,   d_wthi);
    cudaGetSymbolAddress((void**)&wtlo,   d_wtlo);

    cudaFuncSetAttribute(sage_mma_gemm_kernel,
                         cudaFuncAttributeMaxDynamicSharedMemorySize, GEMM_SMEM);

    const int* src = ei;
    const int* dst = ei + EE;

    embed_kernel<<<(NN * 32 + 255) / 256, 256>>>(z, z_emb, x, xh);
    zero_count_kernel<<<(NN + 255) / 256, 256>>>(count);
    hist_kernel<<<(EE + 255) / 256, 256>>>(dst, count);
    scan_blocks_kernel<<<NBLK, 1024>>>(count, rowptr, partial);
    scan_partials_kernel<<<1, 32>>>(partial);
    scan_finalize_kernel<<<NBLK, 1024>>>(count, partial, rowptr, cursor, deginv);
    fill_csr_kernel<<<(EE + 255) / 256, 256>>>(src, dst, cursor, csrsrc);
    graph_starts_kernel<<<3, 256>>>(batch, start);
    for (int l = 0; l < 3; l++)
        wcvt_kernel<<<128, 256>>>(Wl[l], Wr[l],
                                  wthi + (size_t)l * 32768, wtlo + (size_t)l * 32768);

    float *cur = x, *nxt = y;
    __half *curh = xh, *nxth = yh;
    for (int l = 0; l < 3; l++) {
        aggregate_kernel<<<(NN + 7) / 8, dim3(32, 8)>>>(curh, rowptr, csrsrc, deginv, agg);
        sage_mma_gemm_kernel<<<GEMM_BLOCKS, 256, GEMM_SMEM>>>(
            agg, cur, wthi + (size_t)l * 32768, wtlo + (size_t)l * 32768,
            bl[l], nxt, nxth, NN, (l < 2) ? 1 : 0);
        float* t; __half* th;
        t = cur; cur = nxt; nxt = t;
        th = curh; curh = nxth; nxth = th;
    }

    pool_kernel<<<GG, dim3(32, 8)>>>(cur, start, g);
    mlp_kernel<<<GG, 128>>>(g, W1, b1, W2, b2, out);
}

// round 8
// speedup vs baseline: 1.0073x; 1.0002x over previous
#include <cuda_runtime.h>
#include <cuda_bf16.h>
#include <cstdint>
#include <cstdio>

#define NN 50000
#define EE 800000
#define HH 128
#define GG 512
#define NBLK ((NN + 1023) / 1024)        // 49
#define GEMM_BLOCKS ((NN + 127) / 128)   // 391

// ---------------- device scratch (no allocations allowed) ----------------
__device__ float d_x[NN * HH];
__device__ float d_y[NN * HH];
__device__ float d_agg[NN * HH];
__device__ int   d_count[NN];
__device__ int   d_rowptr[NN + 1];
__device__ int   d_cursor[NN];
__device__ int   d_csrsrc[EE];
__device__ float d_deginv[NN];
__device__ int   d_start[GG + 1];
__device__ float d_g[GG * HH];
__device__ int   d_partial[64];
// transposed + bf16-split weights: [3 layers][128 n][256 k]
__device__ __nv_bfloat16 d_wthi[3 * 128 * 256];
__device__ __nv_bfloat16 d_wtlo[3 * 128 * 256];

// ---------------- helpers ----------------
__device__ __forceinline__ float4 add4(float4 a, float4 b) {
    return make_float4(a.x + b.x, a.y + b.y, a.z + b.z, a.w + b.w);
}
__device__ __forceinline__ uint32_t cvta_smem(const void* p) {
    uint32_t a;
    asm("{ .reg .u64 t; cvta.to.shared.u64 t, %1; cvt.u32.u64 %0, t; }" : "=r"(a) : "l"(p));
    return a;
}
__device__ __forceinline__ void ldsm4(uint32_t* r, uint32_t addr) {
    asm volatile("ldmatrix.sync.aligned.m8n8.x4.shared.b16 {%0,%1,%2,%3}, [%4];"
                 : "=r"(r[0]), "=r"(r[1]), "=r"(r[2]), "=r"(r[3]) : "r"(addr));
}
__device__ __forceinline__ void mma16816(float* c, const uint32_t* a, const uint32_t* b) {
    asm volatile(
        "mma.sync.aligned.m16n8k16.row.col.f32.bf16.bf16.f32 "
        "{%0,%1,%2,%3}, {%4,%5,%6,%7}, {%8,%9}, {%0,%1,%2,%3};"
        : "+f"(c[0]), "+f"(c[1]), "+f"(c[2]), "+f"(c[3])
        : "r"(a[0]), "r"(a[1]), "r"(a[2]), "r"(a[3]), "r"(b[0]), "r"(b[1]));
}

// ---------------- embedding gather ----------------
__global__ void embed_kernel(const int* __restrict__ z,
                             const float* __restrict__ z_emb,
                             float* __restrict__ x) {
    int idx = blockIdx.x * blockDim.x + threadIdx.x;
    if (idx >= NN * 32) return;
    int n  = idx >> 5;
    int c4 = idx & 31;
    int zn = z[n];
    const float4* src = reinterpret_cast<const float4*>(z_emb) + (size_t)zn * 32 + c4;
    reinterpret_cast<float4*>(x)[idx] = *src;
}

__global__ void zero_count_kernel(int* __restrict__ count) {
    int i = blockIdx.x * blockDim.x + threadIdx.x;
    if (i < NN) count[i] = 0;
}

__global__ void hist_kernel(const int* __restrict__ dst, int* __restrict__ count) {
    int e = blockIdx.x * blockDim.x + threadIdx.x;
    if (e < EE) atomicAdd(&count[dst[e]], 1);
}

// ---------------- parallel 3-phase scan ----------------
__global__ __launch_bounds__(1024)
void scan_blocks_kernel(const int* __restrict__ count,
                        int* __restrict__ rowptr,
                        int* __restrict__ partial) {
    __shared__ int warp_sums[32];
    int gid = blockIdx.x * 1024 + threadIdx.x;
    int lane = threadIdx.x & 31;
    int wid  = threadIdx.x >> 5;
    int v = (gid < NN) ? count[gid] : 0;
    int incl = v;
    #pragma unroll
    for (int off = 1; off < 32; off <<= 1) {
        int t = __shfl_up_sync(0xFFFFFFFFu, incl, off);
        if (lane >= off) incl += t;
    }
    if (lane == 31) warp_sums[wid] = incl;
    __syncthreads();
    if (wid == 0) {
        int ws = warp_sums[lane];
        #pragma unroll
        for (int off = 1; off < 32; off <<= 1) {
            int t = __shfl_up_sync(0xFFFFFFFFu, ws, off);
            if (lane >= off) ws += t;
        }
        warp_sums[lane] = ws;
    }
    __syncthreads();
    int excl = incl - v + (wid > 0 ? warp_sums[wid - 1] : 0);
    if (gid < NN) rowptr[gid] = excl;
    if (threadIdx.x == 1023) partial[blockIdx.x] = excl + v;
}

__global__ void scan_partials_kernel(int* __restrict__ partial) {
    int lane = threadIdx.x;
    int carry = 0;
    for (int base = 0; base < NBLK; base += 32) {
        int i = base + lane;
        int v = (i < NBLK) ? partial[i] : 0;
        int incl = v;
        #pragma unroll
        for (int off = 1; off < 32; off <<= 1) {
            int t = __shfl_up_sync(0xFFFFFFFFu, incl, off);
            if (lane >= off) incl += t;
        }
        if (i < NBLK) partial[i] = incl - v + carry;
        carry += __shfl_sync(0xFFFFFFFFu, incl, 31);
    }
}

__global__ __launch_bounds__(1024)
void scan_finalize_kernel(const int* __restrict__ count,
                          const int* __restrict__ partial,
                          int* __restrict__ rowptr,
                          int* __restrict__ cursor,
                          float* __restrict__ deginv) {
    int gid = blockIdx.x * 1024 + threadIdx.x;
    if (gid < NN) {
        int r = rowptr[gid] + partial[blockIdx.x];
        rowptr[gid] = r;
        cursor[gid] = r;
        deginv[gid] = 1.0f / (float)max(count[gid], 1);
    }
    if (gid == 0) rowptr[NN] = EE;
}

__global__ void fill_csr_kernel(const int* __restrict__ src,
                                const int* __restrict__ dst,
                                int* __restrict__ cursor,
                                int* __restrict__ csrsrc) {
    int e = blockIdx.x * blockDim.x + threadIdx.x;
    if (e >= EE) return;
    int d = dst[e];
    int pos = atomicAdd(&cursor[d], 1);
    csrsrc[pos] = src[e];
}

// ---------------- mean aggregation: warp/node, shfl-broadcast indices -------
// Lane l loads csrsrc[base+l] (coalesced), then all 32 gathers are issued
// back-to-back via shfl broadcast into 4 rotating accumulator chains.
__global__ void aggregate_kernel(const float* __restrict__ x,
                                 const int* __restrict__ rowptr,
                                 const int* __restrict__ csrsrc,
                                 const float* __restrict__ deginv,
                                 float* __restrict__ out) {
    int node = blockIdx.x * blockDim.y + threadIdx.y;
    if (node >= NN) return;
    int lane = threadIdx.x;
    int beg = rowptr[node];
    int end = rowptr[node + 1];
    float4 a0 = make_float4(0, 0, 0, 0);
    float4 a1 = make_float4(0, 0, 0, 0);
    float4 a2 = make_float4(0, 0, 0, 0);
    float4 a3 = make_float4(0, 0, 0, 0);
    for (int base = beg; base < end; base += 32) {
        int nn = end - base;
        if (nn > 32) nn = 32;
        int idx = (lane < nn) ? __ldg(&csrsrc[base + lane]) : 0;
        int j = 0;
        for (; j + 3 < nn; j += 4) {
            int s0 = __shfl_sync(0xFFFFFFFFu, idx, j);
            int s1 = __shfl_sync(0xFFFFFFFFu, idx, j + 1);
            int s2 = __shfl_sync(0xFFFFFFFFu, idx, j + 2);
            int s3 = __shfl_sync(0xFFFFFFFFu, idx, j + 3);
            float4 v0 = *reinterpret_cast<const float4*>(x + (size_t)s0 * HH + lane * 4);
            float4 v1 = *reinterpret_cast<const float4*>(x + (size_t)s1 * HH + lane * 4);
            float4 v2 = *reinterpret_cast<const float4*>(x + (size_t)s2 * HH + lane * 4);
            float4 v3 = *reinterpret_cast<const float4*>(x + (size_t)s3 * HH + lane * 4);
            a0 = add4(a0, v0);
            a1 = add4(a1, v1);
            a2 = add4(a2, v2);
            a3 = add4(a3, v3);
        }
        for (; j < nn; j++) {
            int s0 = __shfl_sync(0xFFFFFFFFu, idx, j);
            float4 v0 = *reinterpret_cast<const float4*>(x + (size_t)s0 * HH + lane * 4);
            a0 = add4(a0, v0);
        }
    }
    float di = deginv[node];
    float4 acc = add4(add4(a0, a1), add4(a2, a3));
    acc.x *= di; acc.y *= di; acc.z *= di; acc.w *= di;
    *reinterpret_cast<float4*>(out + (size_t)node * HH + lane * 4) = acc;
}

// ---------------- weight transpose + bf16 split ----------------
__global__ void wcvt_kernel(const float* __restrict__ Wl,
                            const float* __restrict__ Wr,
                            __nv_bfloat16* __restrict__ whi,
                            __nv_bfloat16* __restrict__ wlo) {
    int i = blockIdx.x * blockDim.x + threadIdx.x;   // 32768
    if (i >= 32768) return;
    int n = i >> 8;
    int k = i & 255;
    float v = (k < 128) ? Wl[(size_t)k * HH + n] : Wr[(size_t)(k - 128) * HH + n];
    __nv_bfloat16 h = __float2bfloat16(v);
    __nv_bfloat16 l = __float2bfloat16(v - __bfloat162float(h));
    whi[i] = h;
    wlo[i] = l;
}

// ---------------- HMMA SAGE GEMM (identical to R5) ------------------------
#define AST 72   // smem row stride in bf16 elements (144B: conflict-free ldmatrix)
#define SA_HI 0
#define SA_LO 18432
#define SW_HI 36864
#define SW_LO 55296
#define SM_BIAS 73728
#define GEMM_SMEM (73728 + 512)

__global__ __launch_bounds__(256)
void sage_mma_gemm_kernel(const float* __restrict__ A0,   // agg [N,128]
                          const float* __restrict__ A1,   // x   [N,128]
                          const __nv_bfloat16* __restrict__ wthi,  // [128][256]
                          const __nv_bfloat16* __restrict__ wtlo,
                          const float* __restrict__ bias,
                          float* __restrict__ out,
                          int nrows, int do_relu) {
    extern __shared__ char sm[];
    uint32_t sbase = cvta_smem(sm);
    float* bias_sm = (float*)(sm + SM_BIAS);

    int tid  = threadIdx.x;
    int lane = tid & 31;
    int wid  = tid >> 5;
    int warp_m = wid & 3;
    int warp_n = wid >> 2;
    int block_row = blockIdx.x * 128;

    if (tid < 128) bias_sm[tid] = bias[tid];

    int a_row  = warp_m * 32 + ((lane >> 3) & 1) * 8 + (lane & 7);
    int a_colb = (lane >> 4) * 8;
    int b_n    = warp_n * 64 + (lane >> 4) * 8 + (lane & 7);
    int b_kb   = ((lane >> 3) & 1) * 8;

    float acc[2][8][4];
    #pragma unroll
    for (int mf = 0; mf < 2; mf++)
        #pragma unroll
        for (int nf = 0; nf < 8; nf++)
            #pragma unroll
            for (int i = 0; i < 4; i++) acc[mf][nf][i] = 0.0f;

    for (int c = 0; c < 4; c++) {
        if (c > 0) __syncthreads();

        // --- stage A chunk: 128 rows x 64 k, fp32 -> hi/lo bf16 ---
        const float* Asrc = (c < 2) ? A0 : A1;
        int kc = (c & 1) * 64;
        #pragma unroll
        for (int it = 0; it < 8; it++) {
            int i  = tid + it * 256;        // 0..2047 float4s
            int r  = i >> 4;                // 0..127
            int k4 = (i & 15) * 4;          // 0..60
            float4 v = make_float4(0, 0, 0, 0);
            int grow = block_row + r;
            if (grow < nrows)
                v = *reinterpret_cast<const float4*>(Asrc + (size_t)grow * HH + kc + k4);
            __nv_bfloat16 h0 = __float2bfloat16(v.x);
            __nv_bfloat16 h1 = __float2bfloat16(v.y);
            __nv_bfloat16 h2 = __float2bfloat16(v.z);
            __nv_bfloat16 h3 = __float2bfloat16(v.w);
            __nv_bfloat16 l0 = __float2bfloat16(v.x - __bfloat162float(h0));
            __nv_bfloat16 l1 = __float2bfloat16(v.y - __bfloat162float(h1));
            __nv_bfloat16 l2 = __float2bfloat16(v.z - __bfloat162float(h2));
            __nv_bfloat16 l3 = __float2bfloat16(v.w - __bfloat162float(h3));
            uint32_t hp0 = (uint32_t)__bfloat16_as_ushort(h0) | ((uint32_t)__bfloat16_as_ushort(h1) << 16);
            uint32_t hp1 = (uint32_t)__bfloat16_as_ushort(h2) | ((uint32_t)__bfloat16_as_ushort(h3) << 16);
            uint32_t lp0 = (uint32_t)__bfloat16_as_ushort(l0) | ((uint32_t)__bfloat16_as_ushort(l1) << 16);
            uint32_t lp1 = (uint32_t)__bfloat16_as_ushort(l2) | ((uint32_t)__bfloat16_as_ushort(l3) << 16);
            uint32_t boff = (uint32_t)(r * AST + k4) * 2;
            *(uint2*)(sm + SA_HI + boff) = make_uint2(hp0, hp1);
            *(uint2*)(sm + SA_LO + boff) = make_uint2(lp0, lp1);
        }
        // --- stage W chunk: 128 n x 64 k, pre-split bf16 (uint4 = 8 bf16) ---
        #pragma unroll
        for (int it = 0; it < 4; it++) {
            int i  = tid + it * 256;        // 0..1023
            int n  = i >> 3;                // 0..127
            int k8 = (i & 7) * 8;           // 0..56
            size_t goff = (size_t)n * 256 + c * 64 + k8;
            uint32_t boff = (uint32_t)(n * AST + k8) * 2;
            *(uint4*)(sm + SW_HI + boff) = *(const uint4*)(wthi + goff);
            *(uint4*)(sm + SW_LO + boff) = *(const uint4*)(wtlo + goff);
        }
        __syncthreads();

        // --- compute: 4 k16-steps ---
        #pragma unroll
        for (int ks = 0; ks < 4; ks++) {
            uint32_t ah[2][4], al[2][4];
            #pragma unroll
            for (int mf = 0; mf < 2; mf++) {
                uint32_t off = (uint32_t)((a_row + mf * 16) * AST + ks * 16 + a_colb) * 2;
                ldsm4(ah[mf], sbase + SA_HI + off);
                ldsm4(al[mf], sbase + SA_LO + off);
            }
            uint32_t bh[4][4], bl[4][4];
            #pragma unroll
            for (int ng = 0; ng < 4; ng++) {
                uint32_t off = (uint32_t)((b_n + ng * 16) * AST + ks * 16 + b_kb) * 2;
                ldsm4(bh[ng], sbase + SW_HI + off);
                ldsm4(bl[ng], sbase + SW_LO + off);
            }
            #pragma unroll
            for (int mf = 0; mf < 2; mf++) {
                #pragma unroll
                for (int nf = 0; nf < 8; nf++)
                    mma16816(acc[mf][nf], ah[mf], &bh[nf >> 1][(nf & 1) * 2]);
                #pragma unroll
                for (int nf = 0; nf < 8; nf++)
                    mma16816(acc[mf][nf], ah[mf], &bl[nf >> 1][(nf & 1) * 2]);
                #pragma unroll
                for (int nf = 0; nf < 8; nf++)
                    mma16816(acc[mf][nf], al[mf], &bh[nf >> 1][(nf & 1) * 2]);
            }
        }
    }

    // --- epilogue: bias + relu, float2 stores ---
    #pragma unroll
    for (int mf = 0; mf < 2; mf++) {
        int r0 = block_row + warp_m * 32 + mf * 16 + (lane >> 2);
        #pragma unroll
        for (int nf = 0; nf < 8; nf++) {
            int col = warp_n * 64 + nf * 8 + (lane & 3) * 2;
            float2 v0 = make_float2(acc[mf][nf][0] + bias_sm[col],
                                    acc[mf][nf][1] + bias_sm[col + 1]);
            float2 v1 = make_float2(acc[mf][nf][2] + bias_sm[col],
                                    acc[mf][nf][3] + bias_sm[col + 1]);
            if (do_relu) {
                v0.x = fmaxf(v0.x, 0.0f); v0.y = fmaxf(v0.y, 0.0f);
                v1.x = fmaxf(v1.x, 0.0f); v1.y = fmaxf(v1.y, 0.0f);
            }
            if (r0 < nrows)
                *reinterpret_cast<float2*>(out + (size_t)r0 * HH + col) = v0;
            if (r0 + 8 < nrows)
                *reinterpret_cast<float2*>(out + (size_t)(r0 + 8) * HH + col) = v1;
        }
    }
}

// ---------------- pooling ----------------
__global__ void graph_starts_kernel(const int* __restrict__ batch, int* __restrict__ start) {
    int b = blockIdx.x * blockDim.x + threadIdx.x;
    if (b > GG) return;
    if (b == GG) { start[GG] = NN; return; }
    int lo = 0, hi = NN;
    while (lo < hi) {
        int mid = (lo + hi) >> 1;
        if (batch[mid] < b) lo = mid + 1; else hi = mid;
    }
    start[b] = lo;
}

__global__ void pool_kernel(const float* __restrict__ x,
                            const int* __restrict__ start,
                            float* __restrict__ g) {
    int b = blockIdx.x;
    int s = start[b], e = start[b + 1];
    int lane = threadIdx.x;
    int w = threadIdx.y;
    float4 acc = make_float4(0, 0, 0, 0);
    for (int n = s + w; n < e; n += 8) {
        float4 v = *reinterpret_cast<const float4*>(x + (size_t)n * HH + lane * 4);
        acc = add4(acc, v);
    }
    __shared__ float4 sh[8][32];
    sh[w][lane] = acc;
    __syncthreads();
    if (w == 0) {
        float4 t = sh[0][lane];
        #pragma unroll
        for (int i = 1; i < 8; i++) t = add4(t, sh[i][lane]);
        *reinterpret_cast<float4*>(g + (size_t)b * HH + lane * 4) = t;
    }
}

// ---------------- final MLP ----------------
__global__ void mlp_kernel(const float* __restrict__ g,
                           const float* __restrict__ W1,
                           const float* __restrict__ b1,
                           const float* __restrict__ W2,
                           const float* __restrict__ b2,
                           float* __restrict__ out) {
    int b = blockIdx.x;
    int t = threadIdx.x;
    __shared__ float gs[HH];
    gs[t] = g[(size_t)b * HH + t];
    __syncthreads();
    float acc = 0.0f;
    #pragma unroll 8
    for (int k = 0; k < HH; k++)
        acc = fmaf(gs[k], W1[(size_t)k * HH + t], acc);
    float h = fmaxf(acc + b1[t], 0.0f);
    float p = h * W2[t];
    #pragma unroll
    for (int off = 16; off > 0; off >>= 1)
        p += __shfl_xor_sync(0xFFFFFFFFu, p, off);
    __shared__ float ws[4];
    if ((t & 31) == 0) ws[t >> 5] = p;
    __syncthreads();
    if (t == 0) out[b] = ws[0] + ws[1] + ws[2] + ws[3] + b2[0];
}

// ---------------- launch ----------------
extern "C" void kernel_launch(void* const* d_in, const int* in_sizes, int n_in,
                              void* d_out, int out_size) {
    const int*   z     = (const int*)d_in[0];
    const int*   ei    = (const int*)d_in[1];
    const int*   batch = (const int*)d_in[2];
    const float* z_emb = (const float*)d_in[3];
    const float* Wl[3] = {(const float*)d_in[4], (const float*)d_in[7], (const float*)d_in[10]};
    const float* bl[3] = {(const float*)d_in[5], (const float*)d_in[8], (const float*)d_in[11]};
    const float* Wr[3] = {(const float*)d_in[6], (const float*)d_in[9], (const float*)d_in[12]};
    const float* W1 = (const float*)d_in[13];
    const float* b1 = (const float*)d_in[14];
    const float* W2 = (const float*)d_in[15];
    const float* b2 = (const float*)d_in[16];
    float* out = (float*)d_out;

    float *x, *y, *agg, *deginv, *g;
    int *count, *rowptr, *cursor, *csrsrc, *start, *partial;
    __nv_bfloat16 *wthi, *wtlo;
    cudaGetSymbolAddress((void**)&x,      d_x);
    cudaGetSymbolAddress((void**)&y,      d_y);
    cudaGetSymbolAddress((void**)&agg,    d_agg);
    cudaGetSymbolAddress((void**)&deginv, d_deginv);
    cudaGetSymbolAddress((void**)&g,      d_g);
    cudaGetSymbolAddress((void**)&count,  d_count);
    cudaGetSymbolAddress((void**)&rowptr, d_rowptr);
    cudaGetSymbolAddress((void**)&cursor, d_cursor);
    cudaGetSymbolAddress((void**)&csrsrc, d_csrsrc);
    cudaGetSymbolAddress((void**)&start,  d_start);
    cudaGetSymbolAddress((void**)&partial,d_partial);
    cudaGetSymbolAddress((void**)&wthi,   d_wthi);
    cudaGetSymbolAddress((void**)&wtlo,   d_wtlo);

    cudaFuncSetAttribute(sage_mma_gemm_kernel,
                         cudaFuncAttributeMaxDynamicSharedMemorySize, GEMM_SMEM);

    const int* src = ei;
    const int* dst = ei + EE;

    embed_kernel<<<(NN * 32 + 255) / 256, 256>>>(z, z_emb, x);
    zero_count_kernel<<<(NN + 255) / 256, 256>>>(count);
    hist_kernel<<<(EE + 255) / 256, 256>>>(dst, count);
    scan_blocks_kernel<<<NBLK, 1024>>>(count, rowptr, partial);
    scan_partials_kernel<<<1, 32>>>(partial);
    scan_finalize_kernel<<<NBLK, 1024>>>(count, partial, rowptr, cursor, deginv);
    fill_csr_kernel<<<(EE + 255) / 256, 256>>>(src, dst, cursor, csrsrc);
    graph_starts_kernel<<<3, 256>>>(batch, start);
    for (int l = 0; l < 3; l++)
        wcvt_kernel<<<128, 256>>>(Wl[l], Wr[l],
                                  wthi + (size_t)l * 32768, wtlo + (size_t)l * 32768);

    float* cur = x;
    float* nxt = y;
    for (int l = 0; l < 3; l++) {
        aggregate_kernel<<<(NN + 7) / 8, dim3(32, 8)>>>(cur, rowptr, csrsrc, deginv, agg);
        sage_mma_gemm_kernel<<<GEMM_BLOCKS, 256, GEMM_SMEM>>>(
            agg, cur, wthi + (size_t)l * 32768, wtlo + (size_t)l * 32768,
            bl[l], nxt, NN, (l < 2) ? 1 : 0);
        float* tmp = cur; cur = nxt; nxt = tmp;
    }

    pool_kernel<<<GG, dim3(32, 8)>>>(cur, start, g);
    mlp_kernel<<<GG, 128>>>(g, W1, b1, W2, b2, out);
}

// round 10
// speedup vs baseline: 1.0169x; 1.0096x over previous
#include <cuda_runtime.h>
#include <cuda_bf16.h>
#include <cstdint>
#include <cstdio>

#define NN 50000
#define EE 800000
#define HH 128
#define GG 512
#define NBLK ((NN + 1023) / 1024)        // 49
#define GEMM_BLOCKS ((NN + 127) / 128)   // 391

// ---------------- device scratch (no allocations allowed) ----------------
__device__ float d_x[NN * HH];
__device__ float d_y[NN * HH];
__device__ float d_agg[NN * HH];
__device__ int   d_count[NN];
__device__ int   d_rowptr[NN + 1];
__device__ int   d_cursor[NN];
__device__ int   d_csrsrc[EE];
__device__ float d_deginv[NN];
__device__ int   d_start[GG + 1];
__device__ float d_g[GG * HH];
__device__ int   d_partial[64];
// transposed + bf16-split weights: [3 layers][128 n][256 k]
__device__ __nv_bfloat16 d_wthi[3 * 128 * 256];
__device__ __nv_bfloat16 d_wtlo[3 * 128 * 256];

// ---------------- helpers ----------------
__device__ __forceinline__ float4 add4(float4 a, float4 b) {
    return make_float4(a.x + b.x, a.y + b.y, a.z + b.z, a.w + b.w);
}
__device__ __forceinline__ uint32_t cvta_smem(const void* p) {
    uint32_t a;
    asm("{ .reg .u64 t; cvta.to.shared.u64 t, %1; cvt.u32.u64 %0, t; }" : "=r"(a) : "l"(p));
    return a;
}
__device__ __forceinline__ void ldsm4(uint32_t* r, uint32_t addr) {
    asm volatile("ldmatrix.sync.aligned.m8n8.x4.shared.b16 {%0,%1,%2,%3}, [%4];"
                 : "=r"(r[0]), "=r"(r[1]), "=r"(r[2]), "=r"(r[3]) : "r"(addr));
}
__device__ __forceinline__ void mma16816(float* c, const uint32_t* a, const uint32_t* b) {
    asm volatile(
        "mma.sync.aligned.m16n8k16.row.col.f32.bf16.bf16.f32 "
        "{%0,%1,%2,%3}, {%4,%5,%6,%7}, {%8,%9}, {%0,%1,%2,%3};"
        : "+f"(c[0]), "+f"(c[1]), "+f"(c[2]), "+f"(c[3])
        : "r"(a[0]), "r"(a[1]), "r"(a[2]), "r"(a[3]), "r"(b[0]), "r"(b[1]));
}

// ---------------- embedding gather ----------------
__global__ void embed_kernel(const int* __restrict__ z,
                             const float* __restrict__ z_emb,
                             float* __restrict__ x) {
    int idx = blockIdx.x * blockDim.x + threadIdx.x;
    if (idx >= NN * 32) return;
    int n  = idx >> 5;
    int c4 = idx & 31;
    int zn = z[n];
    const float4* src = reinterpret_cast<const float4*>(z_emb) + (size_t)zn * 32 + c4;
    reinterpret_cast<float4*>(x)[idx] = *src;
}

__global__ void zero_count_kernel(int* __restrict__ count) {
    int i = blockIdx.x * blockDim.x + threadIdx.x;
    if (i < NN) count[i] = 0;
}

__global__ void hist_kernel(const int* __restrict__ dst, int* __restrict__ count) {
    int e = blockIdx.x * blockDim.x + threadIdx.x;
    if (e < EE) atomicAdd(&count[dst[e]], 1);
}

// ---------------- parallel 3-phase scan ----------------
__global__ __launch_bounds__(1024)
void scan_blocks_kernel(const int* __restrict__ count,
                        int* __restrict__ rowptr,
                        int* __restrict__ partial) {
    __shared__ int warp_sums[32];
    int gid = blockIdx.x * 1024 + threadIdx.x;
    int lane = threadIdx.x & 31;
    int wid  = threadIdx.x >> 5;
    int v = (gid < NN) ? count[gid] : 0;
    int incl = v;
    #pragma unroll
    for (int off = 1; off < 32; off <<= 1) {
        int t = __shfl_up_sync(0xFFFFFFFFu, incl, off);
        if (lane >= off) incl += t;
    }
    if (lane == 31) warp_sums[wid] = incl;
    __syncthreads();
    if (wid == 0) {
        int ws = warp_sums[lane];
        #pragma unroll
        for (int off = 1; off < 32; off <<= 1) {
            int t = __shfl_up_sync(0xFFFFFFFFu, ws, off);
            if (lane >= off) ws += t;
        }
        warp_sums[lane] = ws;
    }
    __syncthreads();
    int excl = incl - v + (wid > 0 ? warp_sums[wid - 1] : 0);
    if (gid < NN) rowptr[gid] = excl;
    if (threadIdx.x == 1023) partial[blockIdx.x] = excl + v;
}

__global__ void scan_partials_kernel(int* __restrict__ partial) {
    int lane = threadIdx.x;
    int carry = 0;
    for (int base = 0; base < NBLK; base += 32) {
        int i = base + lane;
        int v = (i < NBLK) ? partial[i] : 0;
        int incl = v;
        #pragma unroll
        for (int off = 1; off < 32; off <<= 1) {
            int t = __shfl_up_sync(0xFFFFFFFFu, incl, off);
            if (lane >= off) incl += t;
        }
        if (i < NBLK) partial[i] = incl - v + carry;
        carry += __shfl_sync(0xFFFFFFFFu, incl, 31);
    }
}

__global__ __launch_bounds__(1024)
void scan_finalize_kernel(const int* __restrict__ count,
                          const int* __restrict__ partial,
                          int* __restrict__ rowptr,
                          int* __restrict__ cursor,
                          float* __restrict__ deginv) {
    int gid = blockIdx.x * 1024 + threadIdx.x;
    if (gid < NN) {
        int r = rowptr[gid] + partial[blockIdx.x];
        rowptr[gid] = r;
        cursor[gid] = r;
        deginv[gid] = 1.0f / (float)max(count[gid], 1);
    }
    if (gid == 0) rowptr[NN] = EE;
}

__global__ void fill_csr_kernel(const int* __restrict__ src,
                                const int* __restrict__ dst,
                                int* __restrict__ cursor,
                                int* __restrict__ csrsrc) {
    int e = blockIdx.x * blockDim.x + threadIdx.x;
    if (e >= EE) return;
    int d = dst[e];
    int pos = atomicAdd(&cursor[d], 1);
    csrsrc[pos] = src[e];
}

// ---------------- mean aggregation: warp per node, 4-wide unroll ------------
__global__ void aggregate_kernel(const float* __restrict__ x,
                                 const int* __restrict__ rowptr,
                                 const int* __restrict__ csrsrc,
                                 const float* __restrict__ deginv,
                                 float* __restrict__ out) {
    int node = blockIdx.x * blockDim.y + threadIdx.y;
    if (node >= NN) return;
    int lane = threadIdx.x;
    int beg = rowptr[node];
    int end = rowptr[node + 1];
    float4 a0 = make_float4(0, 0, 0, 0);
    float4 a1 = make_float4(0, 0, 0, 0);
    float4 a2 = make_float4(0, 0, 0, 0);
    float4 a3 = make_float4(0, 0, 0, 0);
    int j = beg;
    for (; j + 3 < end; j += 4) {
        int s0 = __ldg(&csrsrc[j]);
        int s1 = __ldg(&csrsrc[j + 1]);
        int s2 = __ldg(&csrsrc[j + 2]);
        int s3 = __ldg(&csrsrc[j + 3]);
        float4 v0 = *reinterpret_cast<const float4*>(x + (size_t)s0 * HH + lane * 4);
        float4 v1 = *reinterpret_cast<const float4*>(x + (size_t)s1 * HH + lane * 4);
        float4 v2 = *reinterpret_cast<const float4*>(x + (size_t)s2 * HH + lane * 4);
        float4 v3 = *reinterpret_cast<const float4*>(x + (size_t)s3 * HH + lane * 4);
        a0 = add4(a0, v0);
        a1 = add4(a1, v1);
        a2 = add4(a2, v2);
        a3 = add4(a3, v3);
    }
    if (j + 1 < end) {
        int s0 = __ldg(&csrsrc[j]);
        int s1 = __ldg(&csrsrc[j + 1]);
        float4 v0 = *reinterpret_cast<const float4*>(x + (size_t)s0 * HH + lane * 4);
        float4 v1 = *reinterpret_cast<const float4*>(x + (size_t)s1 * HH + lane * 4);
        a0 = add4(a0, v0);
        a1 = add4(a1, v1);
        j += 2;
    }
    if (j < end) {
        int s0 = __ldg(&csrsrc[j]);
        float4 v0 = *reinterpret_cast<const float4*>(x + (size_t)s0 * HH + lane * 4);
        a0 = add4(a0, v0);
    }
    float di = deginv[node];
    float4 acc = add4(add4(a0, a1), add4(a2, a3));
    acc.x *= di; acc.y *= di; acc.z *= di; acc.w *= di;
    *reinterpret_cast<float4*>(out + (size_t)node * HH + lane * 4) = acc;
}

// ---------------- weight transpose + bf16 split ----------------
__global__ void wcvt_kernel(const float* __restrict__ Wl,
                            const float* __restrict__ Wr,
                            __nv_bfloat16* __restrict__ whi,
                            __nv_bfloat16* __restrict__ wlo) {
    int i = blockIdx.x * blockDim.x + threadIdx.x;   // 32768
    if (i >= 32768) return;
    int n = i >> 8;
    int k = i & 255;
    float v = (k < 128) ? Wl[(size_t)k * HH + n] : Wr[(size_t)(k - 128) * HH + n];
    __nv_bfloat16 h = __float2bfloat16(v);
    __nv_bfloat16 l = __float2bfloat16(v - __bfloat162float(h));
    whi[i] = h;
    wlo[i] = l;
}

// ---------------- HMMA SAGE GEMM (identical to R5) ------------------------
#define AST 72   // smem row stride in bf16 elements (144B: conflict-free ldmatrix)
#define SA_HI 0
#define SA_LO 18432
#define SW_HI 36864
#define SW_LO 55296
#define SM_BIAS 73728
#define GEMM_SMEM (73728 + 512)

__global__ __launch_bounds__(256)
void sage_mma_gemm_kernel(const float* __restrict__ A0,   // agg [N,128]
                          const float* __restrict__ A1,   // x   [N,128]
                          const __nv_bfloat16* __restrict__ wthi,  // [128][256]
                          const __nv_bfloat16* __restrict__ wtlo,
                          const float* __restrict__ bias,
                          float* __restrict__ out,
                          int nrows, int do_relu) {
    extern __shared__ char sm[];
    uint32_t sbase = cvta_smem(sm);
    float* bias_sm = (float*)(sm + SM_BIAS);

    int tid  = threadIdx.x;
    int lane = tid & 31;
    int wid  = tid >> 5;
    int warp_m = wid & 3;
    int warp_n = wid >> 2;
    int block_row = blockIdx.x * 128;

    if (tid < 128) bias_sm[tid] = bias[tid];

    int a_row  = warp_m * 32 + ((lane >> 3) & 1) * 8 + (lane & 7);
    int a_colb = (lane >> 4) * 8;
    int b_n    = warp_n * 64 + (lane >> 4) * 8 + (lane & 7);
    int b_kb   = ((lane >> 3) & 1) * 8;

    float acc[2][8][4];
    #pragma unroll
    for (int mf = 0; mf < 2; mf++)
        #pragma unroll
        for (int nf = 0; nf < 8; nf++)
            #pragma unroll
            for (int i = 0; i < 4; i++) acc[mf][nf][i] = 0.0f;

    for (int c = 0; c < 4; c++) {
        if (c > 0) __syncthreads();

        // --- stage A chunk: 128 rows x 64 k, fp32 -> hi/lo bf16 ---
        const float* Asrc = (c < 2) ? A0 : A1;
        int kc = (c & 1) * 64;
        #pragma unroll
        for (int it = 0; it < 8; it++) {
            int i  = tid + it * 256;        // 0..2047 float4s
            int r  = i >> 4;                // 0..127
            int k4 = (i & 15) * 4;          // 0..60
            float4 v = make_float4(0, 0, 0, 0);
            int grow = block_row + r;
            if (grow < nrows)
                v = *reinterpret_cast<const float4*>(Asrc + (size_t)grow * HH + kc + k4);
            __nv_bfloat16 h0 = __float2bfloat16(v.x);
            __nv_bfloat16 h1 = __float2bfloat16(v.y);
            __nv_bfloat16 h2 = __float2bfloat16(v.z);
            __nv_bfloat16 h3 = __float2bfloat16(v.w);
            __nv_bfloat16 l0 = __float2bfloat16(v.x - __bfloat162float(h0));
            __nv_bfloat16 l1 = __float2bfloat16(v.y - __bfloat162float(h1));
            __nv_bfloat16 l2 = __float2bfloat16(v.z - __bfloat162float(h2));
            __nv_bfloat16 l3 = __float2bfloat16(v.w - __bfloat162float(h3));
            uint32_t hp0 = (uint32_t)__bfloat16_as_ushort(h0) | ((uint32_t)__bfloat16_as_ushort(h1) << 16);
            uint32_t hp1 = (uint32_t)__bfloat16_as_ushort(h2) | ((uint32_t)__bfloat16_as_ushort(h3) << 16);
            uint32_t lp0 = (uint32_t)__bfloat16_as_ushort(l0) | ((uint32_t)__bfloat16_as_ushort(l1) << 16);
            uint32_t lp1 = (uint32_t)__bfloat16_as_ushort(l2) | ((uint32_t)__bfloat16_as_ushort(l3) << 16);
            uint32_t boff = (uint32_t)(r * AST + k4) * 2;
            *(uint2*)(sm + SA_HI + boff) = make_uint2(hp0, hp1);
            *(uint2*)(sm + SA_LO + boff) = make_uint2(lp0, lp1);
        }
        // --- stage W chunk: 128 n x 64 k, pre-split bf16 (uint4 = 8 bf16) ---
        #pragma unroll
        for (int it = 0; it < 4; it++) {
            int i  = tid + it * 256;        // 0..1023
            int n  = i >> 3;                // 0..127
            int k8 = (i & 7) * 8;           // 0..56
            size_t goff = (size_t)n * 256 + c * 64 + k8;
            uint32_t boff = (uint32_t)(n * AST + k8) * 2;
            *(uint4*)(sm + SW_HI + boff) = *(const uint4*)(wthi + goff);
            *(uint4*)(sm + SW_LO + boff) = *(const uint4*)(wtlo + goff);
        }
        __syncthreads();

        // --- compute: 4 k16-steps ---
        #pragma unroll
        for (int ks = 0; ks < 4; ks++) {
            uint32_t ah[2][4], al[2][4];
            #pragma unroll
            for (int mf = 0; mf < 2; mf++) {
                uint32_t off = (uint32_t)((a_row + mf * 16) * AST + ks * 16 + a_colb) * 2;
                ldsm4(ah[mf], sbase + SA_HI + off);
                ldsm4(al[mf], sbase + SA_LO + off);
            }
            uint32_t bh[4][4], bl[4][4];
            #pragma unroll
            for (int ng = 0; ng < 4; ng++) {
                uint32_t off = (uint32_t)((b_n + ng * 16) * AST + ks * 16 + b_kb) * 2;
                ldsm4(bh[ng], sbase + SW_HI + off);
                ldsm4(bl[ng], sbase + SW_LO + off);
            }
            #pragma unroll
            for (int mf = 0; mf < 2; mf++) {
                #pragma unroll
                for (int nf = 0; nf < 8; nf++)
                    mma16816(acc[mf][nf], ah[mf], &bh[nf >> 1][(nf & 1) * 2]);
                #pragma unroll
                for (int nf = 0; nf < 8; nf++)
                    mma16816(acc[mf][nf], ah[mf], &bl[nf >> 1][(nf & 1) * 2]);
                #pragma unroll
                for (int nf = 0; nf < 8; nf++)
                    mma16816(acc[mf][nf], al[mf], &bh[nf >> 1][(nf & 1) * 2]);
            }
        }
    }

    // --- epilogue: bias + relu, float2 stores ---
    #pragma unroll
    for (int mf = 0; mf < 2; mf++) {
        int r0 = block_row + warp_m * 32 + mf * 16 + (lane >> 2);
        #pragma unroll
        for (int nf = 0; nf < 8; nf++) {
            int col = warp_n * 64 + nf * 8 + (lane & 3) * 2;
            float2 v0 = make_float2(acc[mf][nf][0] + bias_sm[col],
                                    acc[mf][nf][1] + bias_sm[col + 1]);
            float2 v1 = make_float2(acc[mf][nf][2] + bias_sm[col],
                                    acc[mf][nf][3] + bias_sm[col + 1]);
            if (do_relu) {
                v0.x = fmaxf(v0.x, 0.0f); v0.y = fmaxf(v0.y, 0.0f);
                v1.x = fmaxf(v1.x, 0.0f); v1.y = fmaxf(v1.y, 0.0f);
            }
            if (r0 < nrows)
                *reinterpret_cast<float2*>(out + (size_t)r0 * HH + col) = v0;
            if (r0 + 8 < nrows)
                *reinterpret_cast<float2*>(out + (size_t)(r0 + 8) * HH + col) = v1;
        }
    }
}

// ---------------- pooling ----------------
__global__ void graph_starts_kernel(const int* __restrict__ batch, int* __restrict__ start) {
    int b = blockIdx.x * blockDim.x + threadIdx.x;
    if (b > GG) return;
    if (b == GG) { start[GG] = NN; return; }
    int lo = 0, hi = NN;
    while (lo < hi) {
        int mid = (lo + hi) >> 1;
        if (batch[mid] < b) lo = mid + 1; else hi = mid;
    }
    start[b] = lo;
}

__global__ void pool_kernel(const float* __restrict__ x,
                            const int* __restrict__ start,
                            float* __restrict__ g) {
    int b = blockIdx.x;
    int s = start[b], e = start[b + 1];
    int lane = threadIdx.x;
    int w = threadIdx.y;
    float4 acc = make_float4(0, 0, 0, 0);
    for (int n = s + w; n < e; n += 8) {
        float4 v = *reinterpret_cast<const float4*>(x + (size_t)n * HH + lane * 4);
        acc = add4(acc, v);
    }
    __shared__ float4 sh[8][32];
    sh[w][lane] = acc;
    __syncthreads();
    if (w == 0) {
        float4 t = sh[0][lane];
        #pragma unroll
        for (int i = 1; i < 8; i++) t = add4(t, sh[i][lane]);
        *reinterpret_cast<float4*>(g + (size_t)b * HH + lane * 4) = t;
    }
}

// ---------------- final MLP ----------------
__global__ void mlp_kernel(const float* __restrict__ g,
                           const float* __restrict__ W1,
                           const float* __restrict__ b1,
                           const float* __restrict__ W2,
                           const float* __restrict__ b2,
                           float* __restrict__ out) {
    int b = blockIdx.x;
    int t = threadIdx.x;
    __shared__ float gs[HH];
    gs[t] = g[(size_t)b * HH + t];
    __syncthreads();
    float acc = 0.0f;
    #pragma unroll 8
    for (int k = 0; k < HH; k++)
        acc = fmaf(gs[k], W1[(size_t)k * HH + t], acc);
    float h = fmaxf(acc + b1[t], 0.0f);
    float p = h * W2[t];
    #pragma unroll
    for (int off = 16; off > 0; off >>= 1)
        p += __shfl_xor_sync(0xFFFFFFFFu, p, off);
    __shared__ float ws[4];
    if ((t & 31) == 0) ws[t >> 5] = p;
    __syncthreads();
    if (t == 0) out[b] = ws[0] + ws[1] + ws[2] + ws[3] + b2[0];
}

// ---------------- launch ----------------
extern "C" void kernel_launch(void* const* d_in, const int* in_sizes, int n_in,
                              void* d_out, int out_size) {
    const int*   z     = (const int*)d_in[0];
    const int*   ei    = (const int*)d_in[1];
    const int*   batch = (const int*)d_in[2];
    const float* z_emb = (const float*)d_in[3];
    const float* Wl[3] = {(const float*)d_in[4], (const float*)d_in[7], (const float*)d_in[10]};
    const float* bl[3] = {(const float*)d_in[5], (const float*)d_in[8], (const float*)d_in[11]};
    const float* Wr[3] = {(const float*)d_in[6], (const float*)d_in[9], (const float*)d_in[12]};
    const float* W1 = (const float*)d_in[13];
    const float* b1 = (const float*)d_in[14];
    const float* W2 = (const float*)d_in[15];
    const float* b2 = (const float*)d_in[16];
    float* out = (float*)d_out;

    float *x, *y, *agg, *deginv, *g;
    int *count, *rowptr, *cursor, *csrsrc, *start, *partial;
    __nv_bfloat16 *wthi, *wtlo;
    cudaGetSymbolAddress((void**)&x,      d_x);
    cudaGetSymbolAddress((void**)&y,      d_y);
    cudaGetSymbolAddress((void**)&agg,    d_agg);
    cudaGetSymbolAddress((void**)&deginv, d_deginv);
    cudaGetSymbolAddress((void**)&g,      d_g);
    cudaGetSymbolAddress((void**)&count,  d_count);
    cudaGetSymbolAddress((void**)&rowptr, d_rowptr);
    cudaGetSymbolAddress((void**)&cursor, d_cursor);
    cudaGetSymbolAddress((void**)&csrsrc, d_csrsrc);
    cudaGetSymbolAddress((void**)&start,  d_start);
    cudaGetSymbolAddress((void**)&partial,d_partial);
    cudaGetSymbolAddress((void**)&wthi,   d_wthi);
    cudaGetSymbolAddress((void**)&wtlo,   d_wtlo);

    cudaFuncSetAttribute(sage_mma_gemm_kernel,
                         cudaFuncAttributeMaxDynamicSharedMemorySize, GEMM_SMEM);

    const int* src = ei;
    const int* dst = ei + EE;

    embed_kernel<<<(NN * 32 + 255) / 256, 256>>>(z, z_emb, x);
    zero_count_kernel<<<(NN + 255) / 256, 256>>>(count);
    hist_kernel<<<(EE + 255) / 256, 256>>>(dst, count);
    scan_blocks_kernel<<<NBLK, 1024>>>(count, rowptr, partial);
    scan_partials_kernel<<<1, 32>>>(partial);
    scan_finalize_kernel<<<NBLK, 1024>>>(count, partial, rowptr, cursor, deginv);
    fill_csr_kernel<<<(EE + 255) / 256, 256>>>(src, dst, cursor, csrsrc);
    graph_starts_kernel<<<3, 256>>>(batch, start);
    for (int l = 0; l < 3; l++)
        wcvt_kernel<<<128, 256>>>(Wl[l], Wr[l],
                                  wthi + (size_t)l * 32768, wtlo + (size_t)l * 32768);

    float* cur = x;
    float* nxt = y;
    for (int l = 0; l < 3; l++) {
        aggregate_kernel<<<(NN + 7) / 8, dim3(32, 8)>>>(cur, rowptr, csrsrc, deginv, agg);
        sage_mma_gemm_kernel<<<GEMM_BLOCKS, 256, GEMM_SMEM>>>(
            agg, cur, wthi + (size_t)l * 32768, wtlo + (size_t)l * 32768,
            bl[l], nxt, NN, (l < 2) ? 1 : 0);
        float* tmp = cur; cur = nxt; nxt = tmp;
    }

    pool_kernel<<<GG, dim3(32, 8)>>>(cur, start, g);
    mlp_kernel<<<GG, 128>>>(g, W1, b1, W2, b2, out);
}

// round 12
// speedup vs baseline: 1.1280x; 1.1092x over previous
#include <cuda_runtime.h>
#include <cuda_bf16.h>
#include <cstdint>
#include <cstdio>

#define NN 50000
#define EE 800000
#define HH 128
#define GG 512
#define NBLK ((NN + 1023) / 1024)        // 49
#define GEMM_BLOCKS ((NN + 127) / 128)   // 391

// ---------------- device scratch (no allocations allowed) ----------------
__device__ float d_x[NN * HH];
__device__ float d_y[NN * HH];
__device__ float d_agg[NN * HH];
__device__ int   d_count[NN];
__device__ int   d_rowptr[NN + 1];
__device__ int   d_cursor[NN];
__device__ int   d_csrsrc[EE];
__device__ float d_deginv[NN];
__device__ int   d_start[GG + 1];
__device__ float d_g[GG * HH];
__device__ int   d_partial[64];
// transposed + bf16-split weights: [3 layers][128 n][256 k]
__device__ __nv_bfloat16 d_wthi[3 * 128 * 256];
__device__ __nv_bfloat16 d_wtlo[3 * 128 * 256];

// ---------------- helpers ----------------
__device__ __forceinline__ float4 add4(float4 a, float4 b) {
    return make_float4(a.x + b.x, a.y + b.y, a.z + b.z, a.w + b.w);
}
__device__ __forceinline__ uint32_t cvta_smem(const void* p) {
    uint32_t a;
    asm("{ .reg .u64 t; cvta.to.shared.u64 t, %1; cvt.u32.u64 %0, t; }" : "=r"(a) : "l"(p));
    return a;
}
__device__ __forceinline__ void ldsm4(uint32_t* r, uint32_t addr) {
    asm volatile("ldmatrix.sync.aligned.m8n8.x4.shared.b16 {%0,%1,%2,%3}, [%4];"
                 : "=r"(r[0]), "=r"(r[1]), "=r"(r[2]), "=r"(r[3]) : "r"(addr));
}
__device__ __forceinline__ void mma16816(float* c, const uint32_t* a, const uint32_t* b) {
    asm volatile(
        "mma.sync.aligned.m16n8k16.row.col.f32.bf16.bf16.f32 "
        "{%0,%1,%2,%3}, {%4,%5,%6,%7}, {%8,%9}, {%0,%1,%2,%3};"
        : "+f"(c[0]), "+f"(c[1]), "+f"(c[2]), "+f"(c[3])
        : "r"(a[0]), "r"(a[1]), "r"(a[2]), "r"(a[3]), "r"(b[0]), "r"(b[1]));
}

// ---------------- embedding gather (+ count zeroing folded in) -------------
__global__ void embed_kernel(const int* __restrict__ z,
                             const float* __restrict__ z_emb,
                             float* __restrict__ x,
                             int* __restrict__ count) {
    int idx = blockIdx.x * blockDim.x + threadIdx.x;
    if (idx < NN) count[idx] = 0;
    if (idx >= NN * 32) return;
    int n  = idx >> 5;
    int c4 = idx & 31;
    int zn = z[n];
    const float4* src = reinterpret_cast<const float4*>(z_emb) + (size_t)zn * 32 + c4;
    reinterpret_cast<float4*>(x)[idx] = *src;
}

__global__ void hist_kernel(const int* __restrict__ dst, int* __restrict__ count) {
    int e = blockIdx.x * blockDim.x + threadIdx.x;
    if (e < EE) atomicAdd(&count[dst[e]], 1);
}

// ---------------- parallel 3-phase scan ----------------
__global__ __launch_bounds__(1024)
void scan_blocks_kernel(const int* __restrict__ count,
                        int* __restrict__ rowptr,
                        int* __restrict__ partial) {
    __shared__ int warp_sums[32];
    int gid = blockIdx.x * 1024 + threadIdx.x;
    int lane = threadIdx.x & 31;
    int wid  = threadIdx.x >> 5;
    int v = (gid < NN) ? count[gid] : 0;
    int incl = v;
    #pragma unroll
    for (int off = 1; off < 32; off <<= 1) {
        int t = __shfl_up_sync(0xFFFFFFFFu, incl, off);
        if (lane >= off) incl += t;
    }
    if (lane == 31) warp_sums[wid] = incl;
    __syncthreads();
    if (wid == 0) {
        int ws = warp_sums[lane];
        #pragma unroll
        for (int off = 1; off < 32; off <<= 1) {
            int t = __shfl_up_sync(0xFFFFFFFFu, ws, off);
            if (lane >= off) ws += t;
        }
        warp_sums[lane] = ws;
    }
    __syncthreads();
    int excl = incl - v + (wid > 0 ? warp_sums[wid - 1] : 0);
    if (gid < NN) rowptr[gid] = excl;
    if (threadIdx.x == 1023) partial[blockIdx.x] = excl + v;
}

__global__ void scan_partials_kernel(int* __restrict__ partial) {
    int lane = threadIdx.x;
    int carry = 0;
    for (int base = 0; base < NBLK; base += 32) {
        int i = base + lane;
        int v = (i < NBLK) ? partial[i] : 0;
        int incl = v;
        #pragma unroll
        for (int off = 1; off < 32; off <<= 1) {
            int t = __shfl_up_sync(0xFFFFFFFFu, incl, off);
            if (lane >= off) incl += t;
        }
        if (i < NBLK) partial[i] = incl - v + carry;
        carry += __shfl_sync(0xFFFFFFFFu, incl, 31);
    }
}

__global__ __launch_bounds__(1024)
void scan_finalize_kernel(const int* __restrict__ count,
                          const int* __restrict__ partial,
                          int* __restrict__ rowptr,
                          int* __restrict__ cursor,
                          float* __restrict__ deginv) {
    int gid = blockIdx.x * 1024 + threadIdx.x;
    if (gid < NN) {
        int r = rowptr[gid] + partial[blockIdx.x];
        rowptr[gid] = r;
        cursor[gid] = r;
        deginv[gid] = 1.0f / (float)max(count[gid], 1);
    }
    if (gid == 0) rowptr[NN] = EE;
}

__global__ void fill_csr_kernel(const int* __restrict__ src,
                                const int* __restrict__ dst,
                                int* __restrict__ cursor,
                                int* __restrict__ csrsrc) {
    int e = blockIdx.x * blockDim.x + threadIdx.x;
    if (e >= EE) return;
    int d = dst[e];
    int pos = atomicAdd(&cursor[d], 1);
    csrsrc[pos] = src[e];
}

// ---------------- mean aggregation: warp per destination (EXACT R5) --------
__global__ void aggregate_kernel(const float* __restrict__ x,
                                 const int* __restrict__ rowptr,
                                 const int* __restrict__ csrsrc,
                                 const float* __restrict__ deginv,
                                 float* __restrict__ out) {
    int node = blockIdx.x * blockDim.y + threadIdx.y;
    if (node >= NN) return;
    int lane = threadIdx.x;
    int beg = rowptr[node];
    int end = rowptr[node + 1];
    float4 a0 = make_float4(0, 0, 0, 0);
    float4 a1 = make_float4(0, 0, 0, 0);
    int j = beg;
    for (; j + 1 < end; j += 2) {
        int s0 = __ldg(&csrsrc[j]);
        int s1 = __ldg(&csrsrc[j + 1]);
        float4 v0 = *reinterpret_cast<const float4*>(x + (size_t)s0 * HH + lane * 4);
        float4 v1 = *reinterpret_cast<const float4*>(x + (size_t)s1 * HH + lane * 4);
        a0 = add4(a0, v0);
        a1 = add4(a1, v1);
    }
    if (j < end) {
        int s0 = __ldg(&csrsrc[j]);
        float4 v0 = *reinterpret_cast<const float4*>(x + (size_t)s0 * HH + lane * 4);
        a0 = add4(a0, v0);
    }
    float di = deginv[node];
    float4 acc = add4(a0, a1);
    acc.x *= di; acc.y *= di; acc.z *= di; acc.w *= di;
    *reinterpret_cast<float4*>(out + (size_t)node * HH + lane * 4) = acc;
}

// ---------------- weight transpose + bf16 split (all 3 layers, 1 launch) ---
__global__ void wcvt_kernel(const float* __restrict__ Wl0, const float* __restrict__ Wr0,
                            const float* __restrict__ Wl1, const float* __restrict__ Wr1,
                            const float* __restrict__ Wl2, const float* __restrict__ Wr2,
                            __nv_bfloat16* __restrict__ whi,
                            __nv_bfloat16* __restrict__ wlo) {
    int i = blockIdx.x * blockDim.x + threadIdx.x;   // 3*32768
    if (i >= 3 * 32768) return;
    int l = i >> 15;
    int r = i & 32767;
    int n = r >> 8;
    int k = r & 255;
    const float* Wl = (l == 0) ? Wl0 : (l == 1) ? Wl1 : Wl2;
    const float* Wr = (l == 0) ? Wr0 : (l == 1) ? Wr1 : Wr2;
    float v = (k < 128) ? Wl[(size_t)k * HH + n] : Wr[(size_t)(k - 128) * HH + n];
    __nv_bfloat16 h = __float2bfloat16(v);
    __nv_bfloat16 lo = __float2bfloat16(v - __bfloat162float(h));
    whi[i] = h;
    wlo[i] = lo;
}

// ---------------- HMMA SAGE GEMM (identical to R5) ------------------------
#define AST 72   // smem row stride in bf16 elements (144B: conflict-free ldmatrix)
#define SA_HI 0
#define SA_LO 18432
#define SW_HI 36864
#define SW_LO 55296
#define SM_BIAS 73728
#define GEMM_SMEM (73728 + 512)

__global__ __launch_bounds__(256)
void sage_mma_gemm_kernel(const float* __restrict__ A0,   // agg [N,128]
                          const float* __restrict__ A1,   // x   [N,128]
                          const __nv_bfloat16* __restrict__ wthi,  // [128][256]
                          const __nv_bfloat16* __restrict__ wtlo,
                          const float* __restrict__ bias,
                          float* __restrict__ out,
                          int nrows, int do_relu) {
    extern __shared__ char sm[];
    uint32_t sbase = cvta_smem(sm);
    float* bias_sm = (float*)(sm + SM_BIAS);

    int tid  = threadIdx.x;
    int lane = tid & 31;
    int wid  = tid >> 5;
    int warp_m = wid & 3;
    int warp_n = wid >> 2;
    int block_row = blockIdx.x * 128;

    if (tid < 128) bias_sm[tid] = bias[tid];

    int a_row  = warp_m * 32 + ((lane >> 3) & 1) * 8 + (lane & 7);
    int a_colb = (lane >> 4) * 8;
    int b_n    = warp_n * 64 + (lane >> 4) * 8 + (lane & 7);
    int b_kb   = ((lane >> 3) & 1) * 8;

    float acc[2][8][4];
    #pragma unroll
    for (int mf = 0; mf < 2; mf++)
        #pragma unroll
        for (int nf = 0; nf < 8; nf++)
            #pragma unroll
            for (int i = 0; i < 4; i++) acc[mf][nf][i] = 0.0f;

    for (int c = 0; c < 4; c++) {
        if (c > 0) __syncthreads();

        // --- stage A chunk: 128 rows x 64 k, fp32 -> hi/lo bf16 ---
        const float* Asrc = (c < 2) ? A0 : A1;
        int kc = (c & 1) * 64;
        #pragma unroll
        for (int it = 0; it < 8; it++) {
            int i  = tid + it * 256;        // 0..2047 float4s
            int r  = i >> 4;                // 0..127
            int k4 = (i & 15) * 4;          // 0..60
            float4 v = make_float4(0, 0, 0, 0);
            int grow = block_row + r;
            if (grow < nrows)
                v = *reinterpret_cast<const float4*>(Asrc + (size_t)grow * HH + kc + k4);
            __nv_bfloat16 h0 = __float2bfloat16(v.x);
            __nv_bfloat16 h1 = __float2bfloat16(v.y);
            __nv_bfloat16 h2 = __float2bfloat16(v.z);
            __nv_bfloat16 h3 = __float2bfloat16(v.w);
            __nv_bfloat16 l0 = __float2bfloat16(v.x - __bfloat162float(h0));
            __nv_bfloat16 l1 = __float2bfloat16(v.y - __bfloat162float(h1));
            __nv_bfloat16 l2 = __float2bfloat16(v.z - __bfloat162float(h2));
            __nv_bfloat16 l3 = __float2bfloat16(v.w - __bfloat162float(h3));
            uint32_t hp0 = (uint32_t)__bfloat16_as_ushort(h0) | ((uint32_t)__bfloat16_as_ushort(h1) << 16);
            uint32_t hp1 = (uint32_t)__bfloat16_as_ushort(h2) | ((uint32_t)__bfloat16_as_ushort(h3) << 16);
            uint32_t lp0 = (uint32_t)__bfloat16_as_ushort(l0) | ((uint32_t)__bfloat16_as_ushort(l1) << 16);
            uint32_t lp1 = (uint32_t)__bfloat16_as_ushort(l2) | ((uint32_t)__bfloat16_as_ushort(l3) << 16);
            uint32_t boff = (uint32_t)(r * AST + k4) * 2;
            *(uint2*)(sm + SA_HI + boff) = make_uint2(hp0, hp1);
            *(uint2*)(sm + SA_LO + boff) = make_uint2(lp0, lp1);
        }
        // --- stage W chunk: 128 n x 64 k, pre-split bf16 (uint4 = 8 bf16) ---
        #pragma unroll
        for (int it = 0; it < 4; it++) {
            int i  = tid + it * 256;        // 0..1023
            int n  = i >> 3;                // 0..127
            int k8 = (i & 7) * 8;           // 0..56
            size_t goff = (size_t)n * 256 + c * 64 + k8;
            uint32_t boff = (uint32_t)(n * AST + k8) * 2;
            *(uint4*)(sm + SW_HI + boff) = *(const uint4*)(wthi + goff);
            *(uint4*)(sm + SW_LO + boff) = *(const uint4*)(wtlo + goff);
        }
        __syncthreads();

        // --- compute: 4 k16-steps ---
        #pragma unroll
        for (int ks = 0; ks < 4; ks++) {
            uint32_t ah[2][4], al[2][4];
            #pragma unroll
            for (int mf = 0; mf < 2; mf++) {
                uint32_t off = (uint32_t)((a_row + mf * 16) * AST + ks * 16 + a_colb) * 2;
                ldsm4(ah[mf], sbase + SA_HI + off);
                ldsm4(al[mf], sbase + SA_LO + off);
            }
            uint32_t bh[4][4], bl[4][4];
            #pragma unroll
            for (int ng = 0; ng < 4; ng++) {
                uint32_t off = (uint32_t)((b_n + ng * 16) * AST + ks * 16 + b_kb) * 2;
                ldsm4(bh[ng], sbase + SW_HI + off);
                ldsm4(bl[ng], sbase + SW_LO + off);
            }
            #pragma unroll
            for (int mf = 0; mf < 2; mf++) {
                #pragma unroll
                for (int nf = 0; nf < 8; nf++)
                    mma16816(acc[mf][nf], ah[mf], &bh[nf >> 1][(nf & 1) * 2]);
                #pragma unroll
                for (int nf = 0; nf < 8; nf++)
                    mma16816(acc[mf][nf], ah[mf], &bl[nf >> 1][(nf & 1) * 2]);
                #pragma unroll
                for (int nf = 0; nf < 8; nf++)
                    mma16816(acc[mf][nf], al[mf], &bh[nf >> 1][(nf & 1) * 2]);
            }
        }
    }

    // --- epilogue: bias + relu, float2 stores ---
    #pragma unroll
    for (int mf = 0; mf < 2; mf++) {
        int r0 = block_row + warp_m * 32 + mf * 16 + (lane >> 2);
        #pragma unroll
        for (int nf = 0; nf < 8; nf++) {
            int col = warp_n * 64 + nf * 8 + (lane & 3) * 2;
            float2 v0 = make_float2(acc[mf][nf][0] + bias_sm[col],
                                    acc[mf][nf][1] + bias_sm[col + 1]);
            float2 v1 = make_float2(acc[mf][nf][2] + bias_sm[col],
                                    acc[mf][nf][3] + bias_sm[col + 1]);
            if (do_relu) {
                v0.x = fmaxf(v0.x, 0.0f); v0.y = fmaxf(v0.y, 0.0f);
                v1.x = fmaxf(v1.x, 0.0f); v1.y = fmaxf(v1.y, 0.0f);
            }
            if (r0 < nrows)
                *reinterpret_cast<float2*>(out + (size_t)r0 * HH + col) = v0;
            if (r0 + 8 < nrows)
                *reinterpret_cast<float2*>(out + (size_t)(r0 + 8) * HH + col) = v1;
        }
    }
}

// ---------------- pooling ----------------
__global__ void graph_starts_kernel(const int* __restrict__ batch, int* __restrict__ start) {
    int b = blockIdx.x * blockDim.x + threadIdx.x;
    if (b > GG) return;
    if (b == GG) { start[GG] = NN; return; }
    int lo = 0, hi = NN;
    while (lo < hi) {
        int mid = (lo + hi) >> 1;
        if (batch[mid] < b) lo = mid + 1; else hi = mid;
    }
    start[b] = lo;
}

__global__ void pool_kernel(const float* __restrict__ x,
                            const int* __restrict__ start,
                            float* __restrict__ g) {
    int b = blockIdx.x;
    int s = start[b], e = start[b + 1];
    int lane = threadIdx.x;
    int w = threadIdx.y;
    float4 acc = make_float4(0, 0, 0, 0);
    for (int n = s + w; n < e; n += 8) {
        float4 v = *reinterpret_cast<const float4*>(x + (size_t)n * HH + lane * 4);
        acc = add4(acc, v);
    }
    __shared__ float4 sh[8][32];
    sh[w][lane] = acc;
    __syncthreads();
    if (w == 0) {
        float4 t = sh[0][lane];
        #pragma unroll
        for (int i = 1; i < 8; i++) t = add4(t, sh[i][lane]);
        *reinterpret_cast<float4*>(g + (size_t)b * HH + lane * 4) = t;
    }
}

// ---------------- final MLP ----------------
__global__ void mlp_kernel(const float* __restrict__ g,
                           const float* __restrict__ W1,
                           const float* __restrict__ b1,
                           const float* __restrict__ W2,
                           const float* __restrict__ b2,
                           float* __restrict__ out) {
    int b = blockIdx.x;
    int t = threadIdx.x;
    __shared__ float gs[HH];
    gs[t] = g[(size_t)b * HH + t];
    __syncthreads();
    float acc = 0.0f;
    #pragma unroll 8
    for (int k = 0; k < HH; k++)
        acc = fmaf(gs[k], W1[(size_t)k * HH + t], acc);
    float h = fmaxf(acc + b1[t], 0.0f);
    float p = h * W2[t];
    #pragma unroll
    for (int off = 16; off > 0; off >>= 1)
        p += __shfl_xor_sync(0xFFFFFFFFu, p, off);
    __shared__ float ws[4];
    if ((t & 31) == 0) ws[t >> 5] = p;
    __syncthreads();
    if (t == 0) out[b] = ws[0] + ws[1] + ws[2] + ws[3] + b2[0];
}

// ---------------- launch ----------------
extern "C" void kernel_launch(void* const* d_in, const int* in_sizes, int n_in,
                              void* d_out, int out_size) {
    const int*   z     = (const int*)d_in[0];
    const int*   ei    = (const int*)d_in[1];
    const int*   batch = (const int*)d_in[2];
    const float* z_emb = (const float*)d_in[3];
    const float* Wl[3] = {(const float*)d_in[4], (const float*)d_in[7], (const float*)d_in[10]};
    const float* bl[3] = {(const float*)d_in[5], (const float*)d_in[8], (const float*)d_in[11]};
    const float* Wr[3] = {(const float*)d_in[6], (const float*)d_in[9], (const float*)d_in[12]};
    const float* W1 = (const float*)d_in[13];
    const float* b1 = (const float*)d_in[14];
    const float* W2 = (const float*)d_in[15];
    const float* b2 = (const float*)d_in[16];
    float* out = (float*)d_out;

    float *x, *y, *agg, *deginv, *g;
    int *count, *rowptr, *cursor, *csrsrc, *start, *partial;
    __nv_bfloat16 *wthi, *wtlo;
    cudaGetSymbolAddress((void**)&x,      d_x);
    cudaGetSymbolAddress((void**)&y,      d_y);
    cudaGetSymbolAddress((void**)&agg,    d_agg);
    cudaGetSymbolAddress((void**)&deginv, d_deginv);
    cudaGetSymbolAddress((void**)&g,      d_g);
    cudaGetSymbolAddress((void**)&count,  d_count);
    cudaGetSymbolAddress((void**)&rowptr, d_rowptr);
    cudaGetSymbolAddress((void**)&cursor, d_cursor);
    cudaGetSymbolAddress((void**)&csrsrc, d_csrsrc);
    cudaGetSymbolAddress((void**)&start,  d_start);
    cudaGetSymbolAddress((void**)&partial,d_partial);
    cudaGetSymbolAddress((void**)&wthi,   d_wthi);
    cudaGetSymbolAddress((void**)&wtlo,   d_wtlo);

    cudaFuncSetAttribute(sage_mma_gemm_kernel,
                         cudaFuncAttributeMaxDynamicSharedMemorySize, GEMM_SMEM);

    const int* src = ei;
    const int* dst = ei + EE;

    embed_kernel<<<(NN * 32 + 255) / 256, 256>>>(z, z_emb, x, count);
    hist_kernel<<<(EE + 255) / 256, 256>>>(dst, count);
    scan_blocks_kernel<<<NBLK, 1024>>>(count, rowptr, partial);
    scan_partials_kernel<<<1, 32>>>(partial);
    scan_finalize_kernel<<<NBLK, 1024>>>(count, partial, rowptr, cursor, deginv);
    fill_csr_kernel<<<(EE + 255) / 256, 256>>>(src, dst, cursor, csrsrc);
    graph_starts_kernel<<<3, 256>>>(batch, start);
    wcvt_kernel<<<384, 256>>>(Wl[0], Wr[0], Wl[1], Wr[1], Wl[2], Wr[2], wthi, wtlo);

    float* cur = x;
    float* nxt = y;
    for (int l = 0; l < 3; l++) {
        aggregate_kernel<<<(NN + 7) / 8, dim3(32, 8)>>>(cur, rowptr, csrsrc, deginv, agg);
        sage_mma_gemm_kernel<<<GEMM_BLOCKS, 256, GEMM_SMEM>>>(
            agg, cur, wthi + (size_t)l * 32768, wtlo + (size_t)l * 32768,
            bl[l], nxt, NN, (l < 2) ? 1 : 0);
        float* tmp = cur; cur = nxt; nxt = tmp;
    }

    pool_kernel<<<GG, dim3(32, 8)>>>(cur, start, g);
    mlp_kernel<<<GG, 128>>>(g, W1, b1, W2, b2, out);
}

// round 14
// speedup vs baseline: 1.1281x; 1.0001x over previous
#include <cuda_runtime.h>
#include <cuda_bf16.h>
#include <cstdint>
#include <cstdio>

#define NN 50000
#define EE 800000
#define HH 128
#define GG 512
#define NBLK ((NN + 1023) / 1024)        // 49
#define GEMM_BLOCKS ((NN + 127) / 128)   // 391

// ---------------- device scratch (no allocations allowed) ----------------
__device__ float d_x[NN * HH];
__device__ float d_y[NN * HH];
__device__ float d_agg[NN * HH];
__device__ int   d_count[NN];
__device__ int   d_rowptr[NN + 1];
__device__ int   d_cursor[NN];
__device__ int   d_csrsrc[EE];
__device__ float d_deginv[NN];
__device__ int   d_start[GG + 1];
__device__ float d_g[GG * HH];
__device__ int   d_partial[64];
// transposed + bf16-split weights: [3 layers][128 n][256 k]
__device__ __nv_bfloat16 d_wthi[3 * 128 * 256];
__device__ __nv_bfloat16 d_wtlo[3 * 128 * 256];

// ---------------- helpers ----------------
__device__ __forceinline__ float4 add4(float4 a, float4 b) {
    return make_float4(a.x + b.x, a.y + b.y, a.z + b.z, a.w + b.w);
}
__device__ __forceinline__ uint32_t cvta_smem(const void* p) {
    uint32_t a;
    asm("{ .reg .u64 t; cvta.to.shared.u64 t, %1; cvt.u32.u64 %0, t; }" : "=r"(a) : "l"(p));
    return a;
}
__device__ __forceinline__ void ldsm4(uint32_t* r, uint32_t addr) {
    asm volatile("ldmatrix.sync.aligned.m8n8.x4.shared.b16 {%0,%1,%2,%3}, [%4];"
                 : "=r"(r[0]), "=r"(r[1]), "=r"(r[2]), "=r"(r[3]) : "r"(addr));
}
__device__ __forceinline__ void mma16816(float* c, const uint32_t* a, const uint32_t* b) {
    asm volatile(
        "mma.sync.aligned.m16n8k16.row.col.f32.bf16.bf16.f32 "
        "{%0,%1,%2,%3}, {%4,%5,%6,%7}, {%8,%9}, {%0,%1,%2,%3};"
        : "+f"(c[0]), "+f"(c[1]), "+f"(c[2]), "+f"(c[3])
        : "r"(a[0]), "r"(a[1]), "r"(a[2]), "r"(a[3]), "r"(b[0]), "r"(b[1]));
}

// ---------------- embedding gather (+ count zeroing folded in) -------------
__global__ void embed_kernel(const int* __restrict__ z,
                             const float* __restrict__ z_emb,
                             float* __restrict__ x,
                             int* __restrict__ count) {
    int idx = blockIdx.x * blockDim.x + threadIdx.x;
    if (idx < NN) count[idx] = 0;
    if (idx >= NN * 32) return;
    int n  = idx >> 5;
    int c4 = idx & 31;
    int zn = z[n];
    const float4* src = reinterpret_cast<const float4*>(z_emb) + (size_t)zn * 32 + c4;
    reinterpret_cast<float4*>(x)[idx] = *src;
}

__global__ void hist_kernel(const int* __restrict__ dst, int* __restrict__ count) {
    int e = blockIdx.x * blockDim.x + threadIdx.x;
    if (e < EE) atomicAdd(&count[dst[e]], 1);
}

// ---------------- 2-phase scan: per-block scan + per-block lookback --------
__global__ __launch_bounds__(1024)
void scan_blocks_kernel(const int* __restrict__ count,
                        int* __restrict__ rowptr,
                        int* __restrict__ partial) {
    __shared__ int warp_sums[32];
    int gid = blockIdx.x * 1024 + threadIdx.x;
    int lane = threadIdx.x & 31;
    int wid  = threadIdx.x >> 5;
    int v = (gid < NN) ? count[gid] : 0;
    int incl = v;
    #pragma unroll
    for (int off = 1; off < 32; off <<= 1) {
        int t = __shfl_up_sync(0xFFFFFFFFu, incl, off);
        if (lane >= off) incl += t;
    }
    if (lane == 31) warp_sums[wid] = incl;
    __syncthreads();
    if (wid == 0) {
        int ws = warp_sums[lane];
        #pragma unroll
        for (int off = 1; off < 32; off <<= 1) {
            int t = __shfl_up_sync(0xFFFFFFFFu, ws, off);
            if (lane >= off) ws += t;
        }
        warp_sums[lane] = ws;
    }
    __syncthreads();
    int excl = incl - v + (wid > 0 ? warp_sums[wid - 1] : 0);
    if (gid < NN) rowptr[gid] = excl;
    if (threadIdx.x == 1023) partial[blockIdx.x] = excl + v;   // unscanned block total
}

// finalize with in-kernel lookback: each block sums partial[0..bid-1] itself
__global__ __launch_bounds__(1024)
void scan_finalize_kernel(const int* __restrict__ count,
                          const int* __restrict__ partial,
                          int* __restrict__ rowptr,
                          int* __restrict__ cursor,
                          float* __restrict__ deginv) {
    __shared__ int block_off;
    int tid = threadIdx.x;
    if (tid < 32) {
        int bid = blockIdx.x;
        int s = 0;
        if (tid < bid) s += partial[tid];
        if (tid + 32 < bid) s += partial[tid + 32];
        #pragma unroll
        for (int off = 16; off > 0; off >>= 1)
            s += __shfl_xor_sync(0xFFFFFFFFu, s, off);
        if (tid == 0) block_off = s;
    }
    __syncthreads();
    int gid = blockIdx.x * 1024 + tid;
    if (gid < NN) {
        int r = rowptr[gid] + block_off;
        rowptr[gid] = r;
        cursor[gid] = r;
        deginv[gid] = 1.0f / (float)max(count[gid], 1);
    }
    if (gid == 0) rowptr[NN] = EE;
}

__global__ void fill_csr_kernel(const int* __restrict__ src,
                                const int* __restrict__ dst,
                                int* __restrict__ cursor,
                                int* __restrict__ csrsrc) {
    int e = blockIdx.x * blockDim.x + threadIdx.x;
    if (e >= EE) return;
    int d = dst[e];
    int pos = atomicAdd(&cursor[d], 1);
    csrsrc[pos] = src[e];
}

// ---------------- mean aggregation: warp per destination (EXACT R5) --------
__global__ void aggregate_kernel(const float* __restrict__ x,
                                 const int* __restrict__ rowptr,
                                 const int* __restrict__ csrsrc,
                                 const float* __restrict__ deginv,
                                 float* __restrict__ out) {
    int node = blockIdx.x * blockDim.y + threadIdx.y;
    if (node >= NN) return;
    int lane = threadIdx.x;
    int beg = rowptr[node];
    int end = rowptr[node + 1];
    float4 a0 = make_float4(0, 0, 0, 0);
    float4 a1 = make_float4(0, 0, 0, 0);
    int j = beg;
    for (; j + 1 < end; j += 2) {
        int s0 = __ldg(&csrsrc[j]);
        int s1 = __ldg(&csrsrc[j + 1]);
        float4 v0 = *reinterpret_cast<const float4*>(x + (size_t)s0 * HH + lane * 4);
        float4 v1 = *reinterpret_cast<const float4*>(x + (size_t)s1 * HH + lane * 4);
        a0 = add4(a0, v0);
        a1 = add4(a1, v1);
    }
    if (j < end) {
        int s0 = __ldg(&csrsrc[j]);
        float4 v0 = *reinterpret_cast<const float4*>(x + (size_t)s0 * HH + lane * 4);
        a0 = add4(a0, v0);
    }
    float di = deginv[node];
    float4 acc = add4(a0, a1);
    acc.x *= di; acc.y *= di; acc.z *= di; acc.w *= di;
    *reinterpret_cast<float4*>(out + (size_t)node * HH + lane * 4) = acc;
}

// ---------------- weight transpose + bf16 split (all 3 layers, 1 launch) ---
__global__ void wcvt_kernel(const float* __restrict__ Wl0, const float* __restrict__ Wr0,
                            const float* __restrict__ Wl1, const float* __restrict__ Wr1,
                            const float* __restrict__ Wl2, const float* __restrict__ Wr2,
                            __nv_bfloat16* __restrict__ whi,
                            __nv_bfloat16* __restrict__ wlo) {
    int i = blockIdx.x * blockDim.x + threadIdx.x;   // 3*32768
    if (i >= 3 * 32768) return;
    int l = i >> 15;
    int r = i & 32767;
    int n = r >> 8;
    int k = r & 255;
    const float* Wl = (l == 0) ? Wl0 : (l == 1) ? Wl1 : Wl2;
    const float* Wr = (l == 0) ? Wr0 : (l == 1) ? Wr1 : Wr2;
    float v = (k < 128) ? Wl[(size_t)k * HH + n] : Wr[(size_t)(k - 128) * HH + n];
    __nv_bfloat16 h = __float2bfloat16(v);
    __nv_bfloat16 lo = __float2bfloat16(v - __bfloat162float(h));
    whi[i] = h;
    wlo[i] = lo;
}

// ---------------- HMMA SAGE GEMM (identical to R5) ------------------------
#define AST 72   // smem row stride in bf16 elements (144B: conflict-free ldmatrix)
#define SA_HI 0
#define SA_LO 18432
#define SW_HI 36864
#define SW_LO 55296
#define SM_BIAS 73728
#define GEMM_SMEM (73728 + 512)

__global__ __launch_bounds__(256)
void sage_mma_gemm_kernel(const float* __restrict__ A0,   // agg [N,128]
                          const float* __restrict__ A1,   // x   [N,128]
                          const __nv_bfloat16* __restrict__ wthi,  // [128][256]
                          const __nv_bfloat16* __restrict__ wtlo,
                          const float* __restrict__ bias,
                          float* __restrict__ out,
                          int nrows, int do_relu) {
    extern __shared__ char sm[];
    uint32_t sbase = cvta_smem(sm);
    float* bias_sm = (float*)(sm + SM_BIAS);

    int tid  = threadIdx.x;
    int lane = tid & 31;
    int wid  = tid >> 5;
    int warp_m = wid & 3;
    int warp_n = wid >> 2;
    int block_row = blockIdx.x * 128;

    if (tid < 128) bias_sm[tid] = bias[tid];

    int a_row  = warp_m * 32 + ((lane >> 3) & 1) * 8 + (lane & 7);
    int a_colb = (lane >> 4) * 8;
    int b_n    = warp_n * 64 + (lane >> 4) * 8 + (lane & 7);
    int b_kb   = ((lane >> 3) & 1) * 8;

    float acc[2][8][4];
    #pragma unroll
    for (int mf = 0; mf < 2; mf++)
        #pragma unroll
        for (int nf = 0; nf < 8; nf++)
            #pragma unroll
            for (int i = 0; i < 4; i++) acc[mf][nf][i] = 0.0f;

    for (int c = 0; c < 4; c++) {
        if (c > 0) __syncthreads();

        // --- stage A chunk: 128 rows x 64 k, fp32 -> hi/lo bf16 ---
        const float* Asrc = (c < 2) ? A0 : A1;
        int kc = (c & 1) * 64;
        #pragma unroll
        for (int it = 0; it < 8; it++) {
            int i  = tid + it * 256;        // 0..2047 float4s
            int r  = i >> 4;                // 0..127
            int k4 = (i & 15) * 4;          // 0..60
            float4 v = make_float4(0, 0, 0, 0);
            int grow = block_row + r;
            if (grow < nrows)
                v = *reinterpret_cast<const float4*>(Asrc + (size_t)grow * HH + kc + k4);
            __nv_bfloat16 h0 = __float2bfloat16(v.x);
            __nv_bfloat16 h1 = __float2bfloat16(v.y);
            __nv_bfloat16 h2 = __float2bfloat16(v.z);
            __nv_bfloat16 h3 = __float2bfloat16(v.w);
            __nv_bfloat16 l0 = __float2bfloat16(v.x - __bfloat162float(h0));
            __nv_bfloat16 l1 = __float2bfloat16(v.y - __bfloat162float(h1));
            __nv_bfloat16 l2 = __float2bfloat16(v.z - __bfloat162float(h2));
            __nv_bfloat16 l3 = __float2bfloat16(v.w - __bfloat162float(h3));
            uint32_t hp0 = (uint32_t)__bfloat16_as_ushort(h0) | ((uint32_t)__bfloat16_as_ushort(h1) << 16);
            uint32_t hp1 = (uint32_t)__bfloat16_as_ushort(h2) | ((uint32_t)__bfloat16_as_ushort(h3) << 16);
            uint32_t lp0 = (uint32_t)__bfloat16_as_ushort(l0) | ((uint32_t)__bfloat16_as_ushort(l1) << 16);
            uint32_t lp1 = (uint32_t)__bfloat16_as_ushort(l2) | ((uint32_t)__bfloat16_as_ushort(l3) << 16);
            uint32_t boff = (uint32_t)(r * AST + k4) * 2;
            *(uint2*)(sm + SA_HI + boff) = make_uint2(hp0, hp1);
            *(uint2*)(sm + SA_LO + boff) = make_uint2(lp0, lp1);
        }
        // --- stage W chunk: 128 n x 64 k, pre-split bf16 (uint4 = 8 bf16) ---
        #pragma unroll
        for (int it = 0; it < 4; it++) {
            int i  = tid + it * 256;        // 0..1023
            int n  = i >> 3;                // 0..127
            int k8 = (i & 7) * 8;           // 0..56
            size_t goff = (size_t)n * 256 + c * 64 + k8;
            uint32_t boff = (uint32_t)(n * AST + k8) * 2;
            *(uint4*)(sm + SW_HI + boff) = *(const uint4*)(wthi + goff);
            *(uint4*)(sm + SW_LO + boff) = *(const uint4*)(wtlo + goff);
        }
        __syncthreads();

        // --- compute: 4 k16-steps ---
        #pragma unroll
        for (int ks = 0; ks < 4; ks++) {
            uint32_t ah[2][4], al[2][4];
            #pragma unroll
            for (int mf = 0; mf < 2; mf++) {
                uint32_t off = (uint32_t)((a_row + mf * 16) * AST + ks * 16 + a_colb) * 2;
                ldsm4(ah[mf], sbase + SA_HI + off);
                ldsm4(al[mf], sbase + SA_LO + off);
            }
            uint32_t bh[4][4], bl[4][4];
            #pragma unroll
            for (int ng = 0; ng < 4; ng++) {
                uint32_t off = (uint32_t)((b_n + ng * 16) * AST + ks * 16 + b_kb) * 2;
                ldsm4(bh[ng], sbase + SW_HI + off);
                ldsm4(bl[ng], sbase + SW_LO + off);
            }
            #pragma unroll
            for (int mf = 0; mf < 2; mf++) {
                #pragma unroll
                for (int nf = 0; nf < 8; nf++)
                    mma16816(acc[mf][nf], ah[mf], &bh[nf >> 1][(nf & 1) * 2]);
                #pragma unroll
                for (int nf = 0; nf < 8; nf++)
                    mma16816(acc[mf][nf], ah[mf], &bl[nf >> 1][(nf & 1) * 2]);
                #pragma unroll
                for (int nf = 0; nf < 8; nf++)
                    mma16816(acc[mf][nf], al[mf], &bh[nf >> 1][(nf & 1) * 2]);
            }
        }
    }

    // --- epilogue: bias + relu, float2 stores ---
    #pragma unroll
    for (int mf = 0; mf < 2; mf++) {
        int r0 = block_row + warp_m * 32 + mf * 16 + (lane >> 2);
        #pragma unroll
        for (int nf = 0; nf < 8; nf++) {
            int col = warp_n * 64 + nf * 8 + (lane & 3) * 2;
            float2 v0 = make_float2(acc[mf][nf][0] + bias_sm[col],
                                    acc[mf][nf][1] + bias_sm[col + 1]);
            float2 v1 = make_float2(acc[mf][nf][2] + bias_sm[col],
                                    acc[mf][nf][3] + bias_sm[col + 1]);
            if (do_relu) {
                v0.x = fmaxf(v0.x, 0.0f); v0.y = fmaxf(v0.y, 0.0f);
                v1.x = fmaxf(v1.x, 0.0f); v1.y = fmaxf(v1.y, 0.0f);
            }
            if (r0 < nrows)
                *reinterpret_cast<float2*>(out + (size_t)r0 * HH + col) = v0;
            if (r0 + 8 < nrows)
                *reinterpret_cast<float2*>(out + (size_t)(r0 + 8) * HH + col) = v1;
        }
    }
}

// ---------------- pooling ----------------
__global__ void graph_starts_kernel(const int* __restrict__ batch, int* __restrict__ start) {
    int b = blockIdx.x * blockDim.x + threadIdx.x;
    if (b > GG) return;
    if (b == GG) { start[GG] = NN; return; }
    int lo = 0, hi = NN;
    while (lo < hi) {
        int mid = (lo + hi) >> 1;
        if (batch[mid] < b) lo = mid + 1; else hi = mid;
    }
    start[b] = lo;
}

__global__ void pool_kernel(const float* __restrict__ x,
                            const int* __restrict__ start,
                            float* __restrict__ g) {
    int b = blockIdx.x;
    int s = start[b], e = start[b + 1];
    int lane = threadIdx.x;
    int w = threadIdx.y;
    float4 acc = make_float4(0, 0, 0, 0);
    for (int n = s + w; n < e; n += 8) {
        float4 v = *reinterpret_cast<const float4*>(x + (size_t)n * HH + lane * 4);
        acc = add4(acc, v);
    }
    __shared__ float4 sh[8][32];
    sh[w][lane] = acc;
    __syncthreads();
    if (w == 0) {
        float4 t = sh[0][lane];
        #pragma unroll
        for (int i = 1; i < 8; i++) t = add4(t, sh[i][lane]);
        *reinterpret_cast<float4*>(g + (size_t)b * HH + lane * 4) = t;
    }
}

// ---------------- final MLP ----------------
__global__ void mlp_kernel(const float* __restrict__ g,
                           const float* __restrict__ W1,
                           const float* __restrict__ b1,
                           const float* __restrict__ W2,
                           const float* __restrict__ b2,
                           float* __restrict__ out) {
    int b = blockIdx.x;
    int t = threadIdx.x;
    __shared__ float gs[HH];
    gs[t] = g[(size_t)b * HH + t];
    __syncthreads();
    float acc = 0.0f;
    #pragma unroll 8
    for (int k = 0; k < HH; k++)
        acc = fmaf(gs[k], W1[(size_t)k * HH + t], acc);
    float h = fmaxf(acc + b1[t], 0.0f);
    float p = h * W2[t];
    #pragma unroll
    for (int off = 16; off > 0; off >>= 1)
        p += __shfl_xor_sync(0xFFFFFFFFu, p, off);
    __shared__ float ws[4];
    if ((t & 31) == 0) ws[t >> 5] = p;
    __syncthreads();
    if (t == 0) out[b] = ws[0] + ws[1] + ws[2] + ws[3] + b2[0];
}

// ---------------- launch ----------------
extern "C" void kernel_launch(void* const* d_in, const int* in_sizes, int n_in,
                              void* d_out, int out_size) {
    const int*   z     = (const int*)d_in[0];
    const int*   ei    = (const int*)d_in[1];
    const int*   batch = (const int*)d_in[2];
    const float* z_emb = (const float*)d_in[3];
    const float* Wl[3] = {(const float*)d_in[4], (const float*)d_in[7], (const float*)d_in[10]};
    const float* bl[3] = {(const float*)d_in[5], (const float*)d_in[8], (const float*)d_in[11]};
    const float* Wr[3] = {(const float*)d_in[6], (const float*)d_in[9], (const float*)d_in[12]};
    const float* W1 = (const float*)d_in[13];
    const float* b1 = (const float*)d_in[14];
    const float* W2 = (const float*)d_in[15];
    const float* b2 = (const float*)d_in[16];
    float* out = (float*)d_out;

    float *x, *y, *agg, *deginv, *g;
    int *count, *rowptr, *cursor, *csrsrc, *start, *partial;
    __nv_bfloat16 *wthi, *wtlo;
    cudaGetSymbolAddress((void**)&x,      d_x);
    cudaGetSymbolAddress((void**)&y,      d_y);
    cudaGetSymbolAddress((void**)&agg,    d_agg);
    cudaGetSymbolAddress((void**)&deginv, d_deginv);
    cudaGetSymbolAddress((void**)&g,      d_g);
    cudaGetSymbolAddress((void**)&count,  d_count);
    cudaGetSymbolAddress((void**)&rowptr, d_rowptr);
    cudaGetSymbolAddress((void**)&cursor, d_cursor);
    cudaGetSymbolAddress((void**)&csrsrc, d_csrsrc);
    cudaGetSymbolAddress((void**)&start,  d_start);
    cudaGetSymbolAddress((void**)&partial,d_partial);
    cudaGetSymbolAddress((void**)&wthi,   d_wthi);
    cudaGetSymbolAddress((void**)&wtlo,   d_wtlo);

    cudaFuncSetAttribute(sage_mma_gemm_kernel,
                         cudaFuncAttributeMaxDynamicSharedMemorySize, GEMM_SMEM);

    const int* src = ei;
    const int* dst = ei + EE;

    // launch order arranged so aggregate is the 6th launch (ncu -s 5 -c 1)
    embed_kernel<<<(NN * 32 + 255) / 256, 256>>>(z, z_emb, x, count);           // 1
    hist_kernel<<<(EE + 255) / 256, 256>>>(dst, count);                          // 2
    scan_blocks_kernel<<<NBLK, 1024>>>(count, rowptr, partial);                  // 3
    scan_finalize_kernel<<<NBLK, 1024>>>(count, partial, rowptr, cursor, deginv);// 4
    fill_csr_kernel<<<(EE + 255) / 256, 256>>>(src, dst, cursor, csrsrc);        // 5

    float* cur = x;
    float* nxt = y;
    for (int l = 0; l < 3; l++) {
        aggregate_kernel<<<(NN + 7) / 8, dim3(32, 8)>>>(cur, rowptr, csrsrc, deginv, agg); // 6 on l=0
        if (l == 0) {
            wcvt_kernel<<<384, 256>>>(Wl[0], Wr[0], Wl[1], Wr[1], Wl[2], Wr[2], wthi, wtlo);
            graph_starts_kernel<<<3, 256>>>(batch, start);
        }
        sage_mma_gemm_kernel<<<GEMM_BLOCKS, 256, GEMM_SMEM>>>(
            agg, cur, wthi + (size_t)l * 32768, wtlo + (size_t)l * 32768,
            bl[l], nxt, NN, (l < 2) ? 1 : 0);
        float* tmp = cur; cur = nxt; nxt = tmp;
    }

    pool_kernel<<<GG, dim3(32, 8)>>>(cur, start, g);
    mlp_kernel<<<GG, 128>>>(g, W1, b1, W2, b2, out);
}

// round 15
// speedup vs baseline: 1.1295x; 1.0013x over previous
#include <cuda_runtime.h>
#include <cuda_bf16.h>
#include <cstdint>
#include <cstdio>

#define NN 50000
#define EE 800000
#define HH 128
#define GG 512
#define NBLK ((NN + 1023) / 1024)        // 49
#define GEMM_BLOCKS ((NN + 127) / 128)   // 391

// ---------------- device scratch (no allocations allowed) ----------------
__device__ float d_x[NN * HH];
__device__ float d_y[NN * HH];
__device__ float d_agg[NN * HH];
__device__ int   d_count[NN];
__device__ int   d_rowptr[NN + 1];
__device__ int   d_cursor[NN];
__device__ int   d_csrsrc[EE];
__device__ float d_deginv[NN];
__device__ int   d_start[GG + 1];
__device__ float d_g[GG * HH];
__device__ int   d_partial[64];
// transposed + bf16-split weights: [3 layers][128 n][256 k]
__device__ __nv_bfloat16 d_wthi[3 * 128 * 256];
__device__ __nv_bfloat16 d_wtlo[3 * 128 * 256];

// ---------------- helpers ----------------
__device__ __forceinline__ float4 add4(float4 a, float4 b) {
    return make_float4(a.x + b.x, a.y + b.y, a.z + b.z, a.w + b.w);
}
__device__ __forceinline__ uint32_t cvta_smem(const void* p) {
    uint32_t a;
    asm("{ .reg .u64 t; cvta.to.shared.u64 t, %1; cvt.u32.u64 %0, t; }" : "=r"(a) : "l"(p));
    return a;
}
__device__ __forceinline__ void ldsm4(uint32_t* r, uint32_t addr) {
    asm volatile("ldmatrix.sync.aligned.m8n8.x4.shared.b16 {%0,%1,%2,%3}, [%4];"
                 : "=r"(r[0]), "=r"(r[1]), "=r"(r[2]), "=r"(r[3]) : "r"(addr));
}
__device__ __forceinline__ void mma16816(float* c, const uint32_t* a, const uint32_t* b) {
    asm volatile(
        "mma.sync.aligned.m16n8k16.row.col.f32.bf16.bf16.f32 "
        "{%0,%1,%2,%3}, {%4,%5,%6,%7}, {%8,%9}, {%0,%1,%2,%3};"
        : "+f"(c[0]), "+f"(c[1]), "+f"(c[2]), "+f"(c[3])
        : "r"(a[0]), "r"(a[1]), "r"(a[2]), "r"(a[3]), "r"(b[0]), "r"(b[1]));
}

// ---------------- embedding gather (+ count zeroing folded in) -------------
__global__ void embed_kernel(const int* __restrict__ z,
                             const float* __restrict__ z_emb,
                             float* __restrict__ x,
                             int* __restrict__ count) {
    int idx = blockIdx.x * blockDim.x + threadIdx.x;
    if (idx < NN) count[idx] = 0;
    if (idx >= NN * 32) return;
    int n  = idx >> 5;
    int c4 = idx & 31;
    int zn = z[n];
    const float4* src = reinterpret_cast<const float4*>(z_emb) + (size_t)zn * 32 + c4;
    reinterpret_cast<float4*>(x)[idx] = *src;
}

__global__ void hist_kernel(const int* __restrict__ dst, int* __restrict__ count) {
    int e = blockIdx.x * blockDim.x + threadIdx.x;
    if (e < EE) atomicAdd(&count[dst[e]], 1);
}

// ---------------- 2-phase scan: per-block scan + per-block lookback --------
__global__ __launch_bounds__(1024)
void scan_blocks_kernel(const int* __restrict__ count,
                        int* __restrict__ rowptr,
                        int* __restrict__ partial) {
    __shared__ int warp_sums[32];
    int gid = blockIdx.x * 1024 + threadIdx.x;
    int lane = threadIdx.x & 31;
    int wid  = threadIdx.x >> 5;
    int v = (gid < NN) ? count[gid] : 0;
    int incl = v;
    #pragma unroll
    for (int off = 1; off < 32; off <<= 1) {
        int t = __shfl_up_sync(0xFFFFFFFFu, incl, off);
        if (lane >= off) incl += t;
    }
    if (lane == 31) warp_sums[wid] = incl;
    __syncthreads();
    if (wid == 0) {
        int ws = warp_sums[lane];
        #pragma unroll
        for (int off = 1; off < 32; off <<= 1) {
            int t = __shfl_up_sync(0xFFFFFFFFu, ws, off);
            if (lane >= off) ws += t;
        }
        warp_sums[lane] = ws;
    }
    __syncthreads();
    int excl = incl - v + (wid > 0 ? warp_sums[wid - 1] : 0);
    if (gid < NN) rowptr[gid] = excl;
    if (threadIdx.x == 1023) partial[blockIdx.x] = excl + v;   // unscanned block total
}

// finalize with in-kernel lookback: each block sums partial[0..bid-1] itself
__global__ __launch_bounds__(1024)
void scan_finalize_kernel(const int* __restrict__ count,
                          const int* __restrict__ partial,
                          int* __restrict__ rowptr,
                          int* __restrict__ cursor,
                          float* __restrict__ deginv) {
    __shared__ int block_off;
    int tid = threadIdx.x;
    if (tid < 32) {
        int bid = blockIdx.x;
        int s = 0;
        if (tid < bid) s += partial[tid];
        if (tid + 32 < bid) s += partial[tid + 32];
        #pragma unroll
        for (int off = 16; off > 0; off >>= 1)
            s += __shfl_xor_sync(0xFFFFFFFFu, s, off);
        if (tid == 0) block_off = s;
    }
    __syncthreads();
    int gid = blockIdx.x * 1024 + tid;
    if (gid < NN) {
        int r = rowptr[gid] + block_off;
        rowptr[gid] = r;
        cursor[gid] = r;
        deginv[gid] = 1.0f / (float)max(count[gid], 1);
    }
    if (gid == 0) rowptr[NN] = EE;
}

__global__ void fill_csr_kernel(const int* __restrict__ src,
                                const int* __restrict__ dst,
                                int* __restrict__ cursor,
                                int* __restrict__ csrsrc) {
    int e = blockIdx.x * blockDim.x + threadIdx.x;
    if (e >= EE) return;
    int d = dst[e];
    int pos = atomicAdd(&cursor[d], 1);
    csrsrc[pos] = src[e];
}

// ---------------- mean aggregation: warp per destination (EXACT R5) --------
__global__ void aggregate_kernel(const float* __restrict__ x,
                                 const int* __restrict__ rowptr,
                                 const int* __restrict__ csrsrc,
                                 const float* __restrict__ deginv,
                                 float* __restrict__ out) {
    int node = blockIdx.x * blockDim.y + threadIdx.y;
    if (node >= NN) return;
    int lane = threadIdx.x;
    int beg = rowptr[node];
    int end = rowptr[node + 1];
    float4 a0 = make_float4(0, 0, 0, 0);
    float4 a1 = make_float4(0, 0, 0, 0);
    int j = beg;
    for (; j + 1 < end; j += 2) {
        int s0 = __ldg(&csrsrc[j]);
        int s1 = __ldg(&csrsrc[j + 1]);
        float4 v0 = *reinterpret_cast<const float4*>(x + (size_t)s0 * HH + lane * 4);
        float4 v1 = *reinterpret_cast<const float4*>(x + (size_t)s1 * HH + lane * 4);
        a0 = add4(a0, v0);
        a1 = add4(a1, v1);
    }
    if (j < end) {
        int s0 = __ldg(&csrsrc[j]);
        float4 v0 = *reinterpret_cast<const float4*>(x + (size_t)s0 * HH + lane * 4);
        a0 = add4(a0, v0);
    }
    float di = deginv[node];
    float4 acc = add4(a0, a1);
    acc.x *= di; acc.y *= di; acc.z *= di; acc.w *= di;
    *reinterpret_cast<float4*>(out + (size_t)node * HH + lane * 4) = acc;
}

// ---------------- weight transpose + bf16 split (all 3 layers, 1 launch) ---
__global__ void wcvt_kernel(const float* __restrict__ Wl0, const float* __restrict__ Wr0,
                            const float* __restrict__ Wl1, const float* __restrict__ Wr1,
                            const float* __restrict__ Wl2, const float* __restrict__ Wr2,
                            __nv_bfloat16* __restrict__ whi,
                            __nv_bfloat16* __restrict__ wlo) {
    int i = blockIdx.x * blockDim.x + threadIdx.x;   // 3*32768
    if (i >= 3 * 32768) return;
    int l = i >> 15;
    int r = i & 32767;
    int n = r >> 8;
    int k = r & 255;
    const float* Wl = (l == 0) ? Wl0 : (l == 1) ? Wl1 : Wl2;
    const float* Wr = (l == 0) ? Wr0 : (l == 1) ? Wr1 : Wr2;
    float v = (k < 128) ? Wl[(size_t)k * HH + n] : Wr[(size_t)(k - 128) * HH + n];
    __nv_bfloat16 h = __float2bfloat16(v);
    __nv_bfloat16 lo = __float2bfloat16(v - __bfloat162float(h));
    whi[i] = h;
    wlo[i] = lo;
}

// ---------------- HMMA SAGE GEMM (R5 body; 2 CTAs/SM via launch bounds) ----
#define AST 72   // smem row stride in bf16 elements (144B: conflict-free ldmatrix)
#define SA_HI 0
#define SA_LO 18432
#define SW_HI 36864
#define SW_LO 55296
#define SM_BIAS 73728
#define GEMM_SMEM (73728 + 512)

__global__ __launch_bounds__(256, 2)
void sage_mma_gemm_kernel(const float* __restrict__ A0,   // agg [N,128]
                          const float* __restrict__ A1,   // x   [N,128]
                          const __nv_bfloat16* __restrict__ wthi,  // [128][256]
                          const __nv_bfloat16* __restrict__ wtlo,
                          const float* __restrict__ bias,
                          float* __restrict__ out,
                          int nrows, int do_relu) {
    extern __shared__ char sm[];
    uint32_t sbase = cvta_smem(sm);
    float* bias_sm = (float*)(sm + SM_BIAS);

    int tid  = threadIdx.x;
    int lane = tid & 31;
    int wid  = tid >> 5;
    int warp_m = wid & 3;
    int warp_n = wid >> 2;
    int block_row = blockIdx.x * 128;

    if (tid < 128) bias_sm[tid] = bias[tid];

    int a_row  = warp_m * 32 + ((lane >> 3) & 1) * 8 + (lane & 7);
    int a_colb = (lane >> 4) * 8;
    int b_n    = warp_n * 64 + (lane >> 4) * 8 + (lane & 7);
    int b_kb   = ((lane >> 3) & 1) * 8;

    float acc[2][8][4];
    #pragma unroll
    for (int mf = 0; mf < 2; mf++)
        #pragma unroll
        for (int nf = 0; nf < 8; nf++)
            #pragma unroll
            for (int i = 0; i < 4; i++) acc[mf][nf][i] = 0.0f;

    for (int c = 0; c < 4; c++) {
        if (c > 0) __syncthreads();

        // --- stage A chunk: 128 rows x 64 k, fp32 -> hi/lo bf16 ---
        const float* Asrc = (c < 2) ? A0 : A1;
        int kc = (c & 1) * 64;
        #pragma unroll
        for (int it = 0; it < 8; it++) {
            int i  = tid + it * 256;        // 0..2047 float4s
            int r  = i >> 4;                // 0..127
            int k4 = (i & 15) * 4;          // 0..60
            float4 v = make_float4(0, 0, 0, 0);
            int grow = block_row + r;
            if (grow < nrows)
                v = *reinterpret_cast<const float4*>(Asrc + (size_t)grow * HH + kc + k4);
            __nv_bfloat16 h0 = __float2bfloat16(v.x);
            __nv_bfloat16 h1 = __float2bfloat16(v.y);
            __nv_bfloat16 h2 = __float2bfloat16(v.z);
            __nv_bfloat16 h3 = __float2bfloat16(v.w);
            __nv_bfloat16 l0 = __float2bfloat16(v.x - __bfloat162float(h0));
            __nv_bfloat16 l1 = __float2bfloat16(v.y - __bfloat162float(h1));
            __nv_bfloat16 l2 = __float2bfloat16(v.z - __bfloat162float(h2));
            __nv_bfloat16 l3 = __float2bfloat16(v.w - __bfloat162float(h3));
            uint32_t hp0 = (uint32_t)__bfloat16_as_ushort(h0) | ((uint32_t)__bfloat16_as_ushort(h1) << 16);
            uint32_t hp1 = (uint32_t)__bfloat16_as_ushort(h2) | ((uint32_t)__bfloat16_as_ushort(h3) << 16);
            uint32_t lp0 = (uint32_t)__bfloat16_as_ushort(l0) | ((uint32_t)__bfloat16_as_ushort(l1) << 16);
            uint32_t lp1 = (uint32_t)__bfloat16_as_ushort(l2) | ((uint32_t)__bfloat16_as_ushort(l3) << 16);
            uint32_t boff = (uint32_t)(r * AST + k4) * 2;
            *(uint2*)(sm + SA_HI + boff) = make_uint2(hp0, hp1);
            *(uint2*)(sm + SA_LO + boff) = make_uint2(lp0, lp1);
        }
        // --- stage W chunk: 128 n x 64 k, pre-split bf16 (uint4 = 8 bf16) ---
        #pragma unroll
        for (int it = 0; it < 4; it++) {
            int i  = tid + it * 256;        // 0..1023
            int n  = i >> 3;                // 0..127
            int k8 = (i & 7) * 8;           // 0..56
            size_t goff = (size_t)n * 256 + c * 64 + k8;
            uint32_t boff = (uint32_t)(n * AST + k8) * 2;
            *(uint4*)(sm + SW_HI + boff) = *(const uint4*)(wthi + goff);
            *(uint4*)(sm + SW_LO + boff) = *(const uint4*)(wtlo + goff);
        }
        __syncthreads();

        // --- compute: 4 k16-steps ---
        #pragma unroll
        for (int ks = 0; ks < 4; ks++) {
            uint32_t ah[2][4], al[2][4];
            #pragma unroll
            for (int mf = 0; mf < 2; mf++) {
                uint32_t off = (uint32_t)((a_row + mf * 16) * AST + ks * 16 + a_colb) * 2;
                ldsm4(ah[mf], sbase + SA_HI + off);
                ldsm4(al[mf], sbase + SA_LO + off);
            }
            uint32_t bh[4][4], bl[4][4];
            #pragma unroll
            for (int ng = 0; ng < 4; ng++) {
                uint32_t off = (uint32_t)((b_n + ng * 16) * AST + ks * 16 + b_kb) * 2;
                ldsm4(bh[ng], sbase + SW_HI + off);
                ldsm4(bl[ng], sbase + SW_LO + off);
            }
            #pragma unroll
            for (int mf = 0; mf < 2; mf++) {
                #pragma unroll
                for (int nf = 0; nf < 8; nf++)
                    mma16816(acc[mf][nf], ah[mf], &bh[nf >> 1][(nf & 1) * 2]);
                #pragma unroll
                for (int nf = 0; nf < 8; nf++)
                    mma16816(acc[mf][nf], ah[mf], &bl[nf >> 1][(nf & 1) * 2]);
                #pragma unroll
                for (int nf = 0; nf < 8; nf++)
                    mma16816(acc[mf][nf], al[mf], &bh[nf >> 1][(nf & 1) * 2]);
            }
        }
    }

    // --- epilogue: bias + relu, float2 stores ---
    #pragma unroll
    for (int mf = 0; mf < 2; mf++) {
        int r0 = block_row + warp_m * 32 + mf * 16 + (lane >> 2);
        #pragma unroll
        for (int nf = 0; nf < 8; nf++) {
            int col = warp_n * 64 + nf * 8 + (lane & 3) * 2;
            float2 v0 = make_float2(acc[mf][nf][0] + bias_sm[col],
                                    acc[mf][nf][1] + bias_sm[col + 1]);
            float2 v1 = make_float2(acc[mf][nf][2] + bias_sm[col],
                                    acc[mf][nf][3] + bias_sm[col + 1]);
            if (do_relu) {
                v0.x = fmaxf(v0.x, 0.0f); v0.y = fmaxf(v0.y, 0.0f);
                v1.x = fmaxf(v1.x, 0.0f); v1.y = fmaxf(v1.y, 0.0f);
            }
            if (r0 < nrows)
                *reinterpret_cast<float2*>(out + (size_t)r0 * HH + col) = v0;
            if (r0 + 8 < nrows)
                *reinterpret_cast<float2*>(out + (size_t)(r0 + 8) * HH + col) = v1;
        }
    }
}

// ---------------- pooling ----------------
__global__ void graph_starts_kernel(const int* __restrict__ batch, int* __restrict__ start) {
    int b = blockIdx.x * blockDim.x + threadIdx.x;
    if (b > GG) return;
    if (b == GG) { start[GG] = NN; return; }
    int lo = 0, hi = NN;
    while (lo < hi) {
        int mid = (lo + hi) >> 1;
        if (batch[mid] < b) lo = mid + 1; else hi = mid;
    }
    start[b] = lo;
}

__global__ void pool_kernel(const float* __restrict__ x,
                            const int* __restrict__ start,
                            float* __restrict__ g) {
    int b = blockIdx.x;
    int s = start[b], e = start[b + 1];
    int lane = threadIdx.x;
    int w = threadIdx.y;
    float4 acc = make_float4(0, 0, 0, 0);
    for (int n = s + w; n < e; n += 8) {
        float4 v = *reinterpret_cast<const float4*>(x + (size_t)n * HH + lane * 4);
        acc = add4(acc, v);
    }
    __shared__ float4 sh[8][32];
    sh[w][lane] = acc;
    __syncthreads();
    if (w == 0) {
        float4 t = sh[0][lane];
        #pragma unroll
        for (int i = 1; i < 8; i++) t = add4(t, sh[i][lane]);
        *reinterpret_cast<float4*>(g + (size_t)b * HH + lane * 4) = t;
    }
}

// ---------------- final MLP ----------------
__global__ void mlp_kernel(const float* __restrict__ g,
                           const float* __restrict__ W1,
                           const float* __restrict__ b1,
                           const float* __restrict__ W2,
                           const float* __restrict__ b2,
                           float* __restrict__ out) {
    int b = blockIdx.x;
    int t = threadIdx.x;
    __shared__ float gs[HH];
    gs[t] = g[(size_t)b * HH + t];
    __syncthreads();
    float acc = 0.0f;
    #pragma unroll 8
    for (int k = 0; k < HH; k++)
        acc = fmaf(gs[k], W1[(size_t)k * HH + t], acc);
    float h = fmaxf(acc + b1[t], 0.0f);
    float p = h * W2[t];
    #pragma unroll
    for (int off = 16; off > 0; off >>= 1)
        p += __shfl_xor_sync(0xFFFFFFFFu, p, off);
    __shared__ float ws[4];
    if ((t & 31) == 0) ws[t >> 5] = p;
    __syncthreads();
    if (t == 0) out[b] = ws[0] + ws[1] + ws[2] + ws[3] + b2[0];
}

// ---------------- launch ----------------
extern "C" void kernel_launch(void* const* d_in, const int* in_sizes, int n_in,
                              void* d_out, int out_size) {
    const int*   z     = (const int*)d_in[0];
    const int*   ei    = (const int*)d_in[1];
    const int*   batch = (const int*)d_in[2];
    const float* z_emb = (const float*)d_in[3];
    const float* Wl[3] = {(const float*)d_in[4], (const float*)d_in[7], (const float*)d_in[10]};
    const float* bl[3] = {(const float*)d_in[5], (const float*)d_in[8], (const float*)d_in[11]};
    const float* Wr[3] = {(const float*)d_in[6], (const float*)d_in[9], (const float*)d_in[12]};
    const float* W1 = (const float*)d_in[13];
    const float* b1 = (const float*)d_in[14];
    const float* W2 = (const float*)d_in[15];
    const float* b2 = (const float*)d_in[16];
    float* out = (float*)d_out;

    float *x, *y, *agg, *deginv, *g;
    int *count, *rowptr, *cursor, *csrsrc, *start, *partial;
    __nv_bfloat16 *wthi, *wtlo;
    cudaGetSymbolAddress((void**)&x,      d_x);
    cudaGetSymbolAddress((void**)&y,      d_y);
    cudaGetSymbolAddress((void**)&agg,    d_agg);
    cudaGetSymbolAddress((void**)&deginv, d_deginv);
    cudaGetSymbolAddress((void**)&g,      d_g);
    cudaGetSymbolAddress((void**)&count,  d_count);
    cudaGetSymbolAddress((void**)&rowptr, d_rowptr);
    cudaGetSymbolAddress((void**)&cursor, d_cursor);
    cudaGetSymbolAddress((void**)&csrsrc, d_csrsrc);
    cudaGetSymbolAddress((void**)&start,  d_start);
    cudaGetSymbolAddress((void**)&partial,d_partial);
    cudaGetSymbolAddress((void**)&wthi,   d_wthi);
    cudaGetSymbolAddress((void**)&wtlo,   d_wtlo);

    cudaFuncSetAttribute(sage_mma_gemm_kernel,
                         cudaFuncAttributeMaxDynamicSharedMemorySize, GEMM_SMEM);

    const int* src = ei;
    const int* dst = ei + EE;

    embed_kernel<<<(NN * 32 + 255) / 256, 256>>>(z, z_emb, x, count);
    hist_kernel<<<(EE + 255) / 256, 256>>>(dst, count);
    scan_blocks_kernel<<<NBLK, 1024>>>(count, rowptr, partial);
    scan_finalize_kernel<<<NBLK, 1024>>>(count, partial, rowptr, cursor, deginv);
    fill_csr_kernel<<<(EE + 255) / 256, 256>>>(src, dst, cursor, csrsrc);

    float* cur = x;
    float* nxt = y;
    for (int l = 0; l < 3; l++) {
        aggregate_kernel<<<(NN + 7) / 8, dim3(32, 8)>>>(cur, rowptr, csrsrc, deginv, agg);
        if (l == 0) {
            wcvt_kernel<<<384, 256>>>(Wl[0], Wr[0], Wl[1], Wr[1], Wl[2], Wr[2], wthi, wtlo);
            graph_starts_kernel<<<3, 256>>>(batch, start);
        }
        sage_mma_gemm_kernel<<<GEMM_BLOCKS, 256, GEMM_SMEM>>>(
            agg, cur, wthi + (size_t)l * 32768, wtlo + (size_t)l * 32768,
            bl[l], nxt, NN, (l < 2) ? 1 : 0);
        float* tmp = cur; cur = nxt; nxt = tmp;
    }

    pool_kernel<<<GG, dim3(32, 8)>>>(cur, start, g);
    mlp_kernel<<<GG, 128>>>(g, W1, b1, W2, b2, out);
}